// round 14
// baseline (speedup 1.0000x reference)
#include <cuda_runtime.h>
#include <cuda_bf16.h>

#define BB  4
#define TT  1024
#define DD  256
#define HH  8
#define CC  16
#define BT  (BB*TT)

typedef unsigned long long ull;

__device__ __forceinline__ unsigned smem_u32(const void* p) {
    unsigned a;
    asm("{ .reg .u64 t; cvta.to.shared.u64 t, %1; cvt.u32.u64 %0, t; }" : "=r"(a) : "l"(p));
    return a;
}
__device__ __forceinline__ void ldsm4(unsigned* r, unsigned addr) {
    asm volatile("ldmatrix.sync.aligned.m8n8.x4.shared.b16 {%0,%1,%2,%3}, [%4];"
                 : "=r"(r[0]), "=r"(r[1]), "=r"(r[2]), "=r"(r[3]) : "r"(addr));
}
__device__ __forceinline__ void mma16816(float* c, const unsigned* a, const unsigned* b) {
    asm volatile("mma.sync.aligned.m16n8k16.row.col.f32.bf16.bf16.f32 "
                 "{%0,%1,%2,%3}, {%4,%5,%6,%7}, {%8,%9}, {%0,%1,%2,%3};"
                 : "+f"(c[0]), "+f"(c[1]), "+f"(c[2]), "+f"(c[3])
                 : "r"(a[0]), "r"(a[1]), "r"(a[2]), "r"(a[3]), "r"(b[0]), "r"(b[1]));
}
__device__ __forceinline__ unsigned cvt2bf(float hi, float lo) {
    unsigned r;
    asm("cvt.rn.bf16x2.f32 %0, %1, %2;" : "=r"(r) : "f"(hi), "f"(lo));
    return r;
}
__device__ __forceinline__ void cpa16(unsigned dst, const void* src) {
    asm volatile("cp.async.cg.shared.global [%0], [%1], 16;" :: "r"(dst), "l"(src));
}
#define CPA_COMMIT() asm volatile("cp.async.commit_group;" ::: "memory")
#define CPA_WAIT0()  asm volatile("cp.async.wait_group 0;" ::: "memory")

// ---------------- scratch ----------------
__device__ float g_qraw[BT*DD];          // FFN scratch
__device__ float g_y[BT*DD];
__device__ float g_zz[BT*DD];
__device__ unsigned char g_mdx[BB*TT*TT];   // u8: 255=masked, else idx 0..254
__device__ float g_lutv[HH*256];
__device__ int   g_mask_flags;
__device__ __nv_bfloat16 g_xhi[BT*DD],  g_xlo[BT*DD];
__device__ __nv_bfloat16 g_athi[BT*DD], g_atlo[BT*DD];
__device__ __nv_bfloat16 g_zhi[BT*DD],  g_zlo[BT*DD];
__device__ __nv_bfloat16 g_whi[5*DD*DD], g_wlo[5*DD*DD];
__device__ __nv_bfloat16 g_vthi[32*HH*BB*TT], g_vtlo[32*HH*BB*TT]; // [bh][32][1024]
__device__ __nv_bfloat16 g_qh2[HH*BB*TT*32], g_ql2[HH*BB*TT*32];   // [bh][t][32]
__device__ __nv_bfloat16 g_kh2[HH*BB*TT*32], g_kl2[HH*BB*TT*32];

// ---------------------------------------------------------------------------
// Merged coef + LUT build. One block per head; block 0 zeroes mask flags.
// ---------------------------------------------------------------------------
__global__ void lut_all(const float* __restrict__ pw1, const float* __restrict__ pb1,
                        const float* __restrict__ pw2, const float* __restrict__ pb2)
{
    __shared__ float sc[34];
    int h = blockIdx.x;
    int t = threadIdx.x;
    if (h == 0 && t == 0) g_mask_flags = 0;
    if (t < 16) {
        float w1 = pw1[h*CC + t], b1 = pb1[h*CC + t], w2 = pw2[h*CC + t];
        float beta, delta, k0add, k1add;
        if (w1 != 0.0f) {
            beta  = 0.495f * w2 * fabsf(w1);
            delta = -b1 / w1;
            k0add = 0.505f * w2 * b1;
            k1add = 0.505f * w2 * w1;
        } else {
            beta = 0.0f; delta = 0.0f;
            k0add = w2 * (0.505f * b1 + 0.495f * fabsf(b1));
            k1add = 0.0f;
        }
        #pragma unroll
        for (int off = 1; off < 16; off <<= 1) {
            k0add += __shfl_xor_sync(0x0000FFFFu, k0add, off);
            k1add += __shfl_xor_sync(0x0000FFFFu, k1add, off);
        }
        sc[2 + t]  = beta;
        sc[18 + t] = delta;
        if (t == 0) {
            sc[0] = pb2[h] + k0add;
            sc[1] = k1add;
        }
    }
    __syncthreads();
    if (t == 255) { g_lutv[h*256 + 255] = 0.0f; return; }
    float m = (t + 0.5f) * (1.0f / 255.0f);
    float v = sc[0] + sc[1] * m;
    #pragma unroll
    for (int c = 0; c < 16; c++)
        v += sc[2 + c] * fabsf(m - sc[18 + c]);
    g_lutv[h*256 + t] = -v;
}

__global__ void detect_kernel(const unsigned* __restrict__ w)
{
    int i = blockIdx.x * blockDim.x + threadIdx.x;
    unsigned x = w[i];
    int f = 0;
    if (x == 0x3F800000u)               f = 2;
    else if ((x & 0xFFFFu) == 0x3F80u)  f = 4;
    else if (x > 1u)                    f = 1;
    if (f) atomicOr(&g_mask_flags, f);
}

__global__ __launch_bounds__(256) void maskfuse_kernel(const float* __restrict__ rd,
                                                       const void* __restrict__ maskp)
{
    int i = blockIdx.x * 256 + threadIdx.x;
    size_t base = (size_t)i * 4;
    int mf = g_mask_flags;
    int mode = (mf & 4) ? 3 : (mf & 2) ? 2 : (mf & 1) ? 1 : 0;
    float4 d4 = *(const float4*)&rd[base];
    int m0, m1, m2, m3;
    if (mode == 0) {
        int4 m = *(const int4*)((const int*)maskp + base);
        m0 = m.x != 0; m1 = m.y != 0; m2 = m.z != 0; m3 = m.w != 0;
    } else if (mode == 1) {
        uchar4 m = *(const uchar4*)((const unsigned char*)maskp + base);
        m0 = m.x != 0; m1 = m.y != 0; m2 = m.z != 0; m3 = m.w != 0;
    } else if (mode == 2) {
        float4 m = *(const float4*)((const float*)maskp + base);
        m0 = m.x != 0.0f; m1 = m.y != 0.0f; m2 = m.z != 0.0f; m3 = m.w != 0.0f;
    } else {
        ushort4 m = *(const ushort4*)((const unsigned short*)maskp + base);
        m0 = m.x != 0; m1 = m.y != 0; m2 = m.z != 0; m3 = m.w != 0;
    }
    int i0 = min(max(__float2int_rd(d4.x * 255.0f), 0), 254);
    int i1 = min(max(__float2int_rd(d4.y * 255.0f), 0), 254);
    int i2 = min(max(__float2int_rd(d4.z * 255.0f), 0), 254);
    int i3 = min(max(__float2int_rd(d4.w * 255.0f), 0), 254);
    uchar4 o;
    o.x = (unsigned char)(m0 ? 255 : i0);
    o.y = (unsigned char)(m1 ? 255 : i1);
    o.z = (unsigned char)(m2 ? 255 : i2);
    o.w = (unsigned char)(m3 ? 255 : i3);
    *(uchar4*)&g_mdx[base] = o;
}

// ---------------------------------------------------------------------------
// Merged split: blocks [0,640) -> weights; blocks [640,2688) -> x.
// ---------------------------------------------------------------------------
__global__ __launch_bounds__(256) void prep_split(const float* __restrict__ x,
                                                  const float* __restrict__ w0,
                                                  const float* __restrict__ w1,
                                                  const float* __restrict__ w2,
                                                  const float* __restrict__ w3,
                                                  const float* __restrict__ w4)
{
    const float* src;
    __nv_bfloat16 *hi, *lo;
    size_t e;
    if (blockIdx.x < 640) {
        int i = blockIdx.x * 256 + threadIdx.x;
        e = (size_t)i * 2;
        int w = (int)(e >> 16);
        size_t off = e & 65535;
        src = ((w == 0) ? w0 : (w == 1) ? w1 : (w == 2) ? w2 : (w == 3) ? w3 : w4) + off - e;
        hi = g_whi; lo = g_wlo;
    } else {
        int i = (blockIdx.x - 640) * 256 + threadIdx.x;
        e = (size_t)i * 2;
        src = x;
        hi = g_xhi; lo = g_xlo;
    }
    float2 v = *(const float2*)&src[e];
    __nv_bfloat16 hx = __float2bfloat16(v.x), hy = __float2bfloat16(v.y);
    __nv_bfloat162 h2; h2.x = hx; h2.y = hy;
    __nv_bfloat162 l2;
    l2.x = __float2bfloat16(v.x - __bfloat162float(hx));
    l2.y = __float2bfloat16(v.y - __bfloat162float(hy));
    *(__nv_bfloat162*)&hi[e] = h2;
    *(__nv_bfloat162*)&lo[e] = l2;
}

// ---------------------------------------------------------------------------
// HMMA GEMM (bf16x3), cp.async double-buffered, PDL-aware.
// ---------------------------------------------------------------------------
#define MM_AHI 0
#define MM_ALO 18432
#define MM_WHI 36864
#define MM_WLO 46080
#define MM_BUF 55296
#define MM_SMEM (2*MM_BUF)

__global__ __launch_bounds__(256) void tcmma(const __nv_bfloat16* __restrict__ Ahi,
                                             const __nv_bfloat16* __restrict__ Alo,
                                             int widx0,
                                             const float* __restrict__ bias,
                                             float* __restrict__ C0,
                                             float* __restrict__ C1,
                                             float* __restrict__ C2,
                                             int act, int qkv)
{
    extern __shared__ char sm[];
    unsigned smb = smem_u32(sm);
    int tid = threadIdx.x;
    int lane = tid & 31;
    int wid = tid >> 5;
    int wm = wid & 3;
    int wn = wid >> 2;
    int m0 = blockIdx.x * 128, n0 = blockIdx.y * 64;
    int z = blockIdx.z;
    const __nv_bfloat16* Whi = g_whi + (size_t)(widx0 + z) * (DD*DD);
    const __nv_bfloat16* Wlo = g_wlo + (size_t)(widx0 + z) * (DD*DD);
    float* C = (z == 0) ? C0 : (z == 1) ? C1 : C2;

    auto stage = [&](int kc, unsigned bo) {
        #pragma unroll
        for (int it = 0; it < 4; it++) {
            int v = tid + it * 256;
            int row = v >> 3, cg = (v & 7) * 8;
            size_t gofs = (size_t)(m0 + row) * 256 + kc * 64 + cg;
            cpa16(smb + bo + MM_AHI + row*144 + cg*2, &Ahi[gofs]);
            cpa16(smb + bo + MM_ALO + row*144 + cg*2, &Alo[gofs]);
        }
        #pragma unroll
        for (int it = 0; it < 2; it++) {
            int v = tid + it * 256;
            int row = v >> 3, cg = (v & 7) * 8;
            size_t gofs = (size_t)(n0 + row) * 256 + kc * 64 + cg;
            cpa16(smb + bo + MM_WHI + row*144 + cg*2, &Whi[gofs]);
            cpa16(smb + bo + MM_WLO + row*144 + cg*2, &Wlo[gofs]);
        }
    };

    float acc[2][4][4];
    #pragma unroll
    for (int a = 0; a < 2; a++)
        #pragma unroll
        for (int b = 0; b < 4; b++)
            #pragma unroll
            for (int c = 0; c < 4; c++) acc[a][b][c] = 0.0f;

    // PDL: wait for predecessor's data before first global read (no-op if not PDL-launched)
    cudaGridDependencySynchronize();

    stage(0, 0);
    CPA_COMMIT();

    for (int kc = 0; kc < 4; kc++) {
        CPA_WAIT0();
        __syncthreads();
        unsigned bo = (unsigned)(kc & 1) * MM_BUF;
        if (kc < 3) { stage(kc + 1, bo ^ MM_BUF); CPA_COMMIT(); }

        #pragma unroll
        for (int ks = 0; ks < 4; ks++) {
            int kb = ks * 16;
            unsigned ah[2][4], al[2][4], bh[2][4], bl[2][4];
            #pragma unroll
            for (int mi = 0; mi < 2; mi++) {
                int row = wm*32 + mi*16 + (lane & 15);
                unsigned ad = smb + bo + MM_AHI + row*144 + (kb + ((lane >> 4) << 3)) * 2;
                ldsm4(ah[mi], ad);
                ldsm4(al[mi], ad + (MM_ALO - MM_AHI));
            }
            #pragma unroll
            for (int gi = 0; gi < 2; gi++) {
                int nrow = wn*32 + gi*16 + (lane & 7) + ((lane >> 4) & 1) * 8;
                unsigned bd = smb + bo + MM_WHI + nrow*144 + (kb + (((lane >> 3) & 1) << 3)) * 2;
                ldsm4(bh[gi], bd);
                ldsm4(bl[gi], bd + (MM_WLO - MM_WHI));
            }
            #pragma unroll
            for (int mi = 0; mi < 2; mi++) {
                #pragma unroll
                for (int ni = 0; ni < 4; ni++) {
                    int gi = ni >> 1, hf = (ni & 1) * 2;
                    mma16816(acc[mi][ni], ah[mi], &bh[gi][hf]);
                    mma16816(acc[mi][ni], ah[mi], &bl[gi][hf]);
                    mma16816(acc[mi][ni], al[mi], &bh[gi][hf]);
                }
            }
        }
    }

    // PDL: allow dependents to launch while we run the epilogue
    cudaTriggerProgrammaticLaunchCompletion();

    if (qkv && z != 2) {
        __nv_bfloat16* dsthi = (z == 0) ? g_qh2 : g_kh2;
        __nv_bfloat16* dstlo = (z == 0) ? g_ql2 : g_kl2;
        int head = blockIdx.y * 2 + wn;
        #pragma unroll
        for (int mi = 0; mi < 2; mi++) {
            #pragma unroll
            for (int rr = 0; rr < 2; rr++) {
                float v[8];
                #pragma unroll
                for (int ni = 0; ni < 4; ni++) {
                    v[ni*2]   = acc[mi][ni][rr*2];
                    v[ni*2+1] = acc[mi][ni][rr*2+1];
                }
                float ss = 0.0f;
                #pragma unroll
                for (int j = 0; j < 8; j++) ss = fmaf(v[j], v[j], ss);
                ss += __shfl_xor_sync(0xffffffffu, ss, 1);
                ss += __shfl_xor_sync(0xffffffffu, ss, 2);
                float inv = 1.0f / fmaxf(sqrtf(ss), 1e-12f);
                int row = m0 + wm*32 + mi*16 + rr*8 + (lane >> 2);
                int b = row >> 10, t = row & 1023;
                size_t base = (((size_t)(b*8 + head)) * 1024 + t) * 32 + (lane & 3) * 2;
                #pragma unroll
                for (int ni = 0; ni < 4; ni++) {
                    float v0 = v[ni*2] * inv, v1 = v[ni*2+1] * inv;
                    unsigned hh = cvt2bf(v1, v0);
                    float f0 = __uint_as_float(hh << 16), f1 = __uint_as_float(hh & 0xFFFF0000u);
                    *(unsigned*)&dsthi[base + ni*8] = hh;
                    *(unsigned*)&dstlo[base + ni*8] = cvt2bf(v1 - f1, v0 - f0);
                }
            }
        }
        return;
    }
    if (qkv) {
        __syncthreads();
        float* sT = (float*)sm;          // [64 cols][132]
        int rbase_l = wm*32 + (lane >> 2);
        int cbase_l = wn*32 + (lane & 3) * 2;
        #pragma unroll
        for (int mi = 0; mi < 2; mi++) {
            #pragma unroll
            for (int ni = 0; ni < 4; ni++) {
                int col = cbase_l + ni*8;
                int row = rbase_l + mi*16;
                sT[(col+0)*132 + row]     = acc[mi][ni][0];
                sT[(col+1)*132 + row]     = acc[mi][ni][1];
                sT[(col+0)*132 + row + 8] = acc[mi][ni][2];
                sT[(col+1)*132 + row + 8] = acc[mi][ni][3];
            }
        }
        __syncthreads();
        int colg = tid >> 2;
        int tr   = (tid & 3) * 32;
        int head = blockIdx.y * 2 + (colg >> 5);
        int c    = colg & 31;
        int b    = m0 >> 10;
        size_t o = (((size_t)(b*8 + head)) * 32 + c) * 1024 + (m0 & 1023) + tr;
        const float* srcp = &sT[colg*132 + tr];
        unsigned hp[16], lp[16];
        #pragma unroll
        for (int j = 0; j < 16; j++) {
            float v0 = srcp[2*j], v1 = srcp[2*j+1];
            unsigned hh = cvt2bf(v1, v0);
            float f0 = __uint_as_float(hh << 16), f1 = __uint_as_float(hh & 0xFFFF0000u);
            hp[j] = hh;
            lp[j] = cvt2bf(v1 - f1, v0 - f0);
        }
        #pragma unroll
        for (int j = 0; j < 4; j++) {
            *(uint4*)&g_vthi[o + j*8] = make_uint4(hp[j*4], hp[j*4+1], hp[j*4+2], hp[j*4+3]);
            *(uint4*)&g_vtlo[o + j*8] = make_uint4(lp[j*4], lp[j*4+1], lp[j*4+2], lp[j*4+3]);
        }
        return;
    }

    int rbase = m0 + wm*32 + (lane >> 2);
    int cbase = n0 + wn*32 + (lane & 3) * 2;
    #pragma unroll
    for (int mi = 0; mi < 2; mi++) {
        #pragma unroll
        for (int ni = 0; ni < 4; ni++) {
            int col = cbase + ni*8;
            float b0 = bias ? bias[col] : 0.0f;
            float b1 = bias ? bias[col + 1] : 0.0f;
            float v0 = acc[mi][ni][0] + b0;
            float v1 = acc[mi][ni][1] + b1;
            float v2 = acc[mi][ni][2] + b0;
            float v3 = acc[mi][ni][3] + b1;
            if (act) {
                v0 = (v0 >= 0.0f) ? v0 : 0.01f * v0;
                v1 = (v1 >= 0.0f) ? v1 : 0.01f * v1;
                v2 = (v2 >= 0.0f) ? v2 : 0.01f * v2;
                v3 = (v3 >= 0.0f) ? v3 : 0.01f * v3;
            }
            int row = rbase + mi*16;
            *(float2*)&C[(size_t)row * 256 + col]       = make_float2(v0, v1);
            *(float2*)&C[(size_t)(row + 8) * 256 + col] = make_float2(v2, v3);
        }
    }
}

// ---------------------------------------------------------------------------
// HMMA attention (PDL trigger added at end of mainloop)
// ---------------------------------------------------------------------------
#define AT_QHI 0
#define AT_QLO 10240
#define AT_KV  20480
#define AT_KVBUF 19456
#define AT_LUT 59392
#define AT_SMEM 60416

__global__ __launch_bounds__(256) void attn_mma_kernel()
{
    extern __shared__ __align__(16) char SM_[];
    unsigned smb = smem_u32(SM_);
    float* sLUT = (float*)(SM_ + AT_LUT);

    int tid = threadIdx.x;
    int lane = tid & 31;
    int wid = tid >> 5;
    int wq = wid & 3;
    int ws = wid >> 2;
    int bh = blockIdx.y, b = bh >> 3, h = bh & 7;
    int t0 = blockIdx.x << 7;

    auto stageKV = [&](int s0, unsigned gb) {
        int row = tid >> 2, cg = (tid & 3) * 8;
        size_t gofs = (((size_t)bh * TT) + s0 + row) * 32 + cg;
        cpa16(smb + gb + 0     + row*80 + cg*2, &g_kh2[gofs]);
        cpa16(smb + gb + 5120  + row*80 + cg*2, &g_kl2[gofs]);
        int c = tid >> 3, sg = (tid & 7) * 8;
        size_t vofs = ((size_t)bh * 32 + c) * 1024 + s0 + sg;
        cpa16(smb + gb + 10240 + c*144 + sg*2, &g_vthi[vofs]);
        cpa16(smb + gb + 14848 + c*144 + sg*2, &g_vtlo[vofs]);
    };

    if (tid < 256) sLUT[tid] = g_lutv[h*256 + tid];
    #pragma unroll
    for (int r2 = 0; r2 < 2; r2++) {
        int row = (tid >> 2) + r2*64, cg = (tid & 3) * 8;
        size_t gofs = (((size_t)bh * TT) + t0 + row) * 32 + cg;
        *(uint4*)(SM_ + AT_QHI + row*80 + cg*2) = *(const uint4*)&g_qh2[gofs];
        *(uint4*)(SM_ + AT_QLO + row*80 + cg*2) = *(const uint4*)&g_ql2[gofs];
    }
    stageKV(0, AT_KV);
    CPA_COMMIT();

    float oacc[2][4][4];
    #pragma unroll
    for (int mi = 0; mi < 2; mi++)
        #pragma unroll
        for (int i = 0; i < 4; i++)
            #pragma unroll
            for (int j = 0; j < 4; j++) oacc[mi][i][j] = 0.0f;
    float zs[2][2] = {{0.f,0.f},{0.f,0.f}};

    int qrow_f = (lane >> 2);
    int ccol_f = (lane & 3) * 2;

    #pragma unroll 1
    for (int st = 0; st < 16; st++) {
        int s0 = st << 6;
        CPA_WAIT0();
        __syncthreads();
        unsigned gb = AT_KV + (unsigned)(st & 1) * AT_KVBUF;
        if (st < 15) { stageKV(s0 + 64, gb == AT_KV ? AT_KV + AT_KVBUF : AT_KV); CPA_COMMIT(); }

        uchar2 md[2][4][2];
        {
            size_t mb = (size_t)b * TT * TT;
            int gcb = s0 + ws*32 + ccol_f;
            #pragma unroll
            for (int mi = 0; mi < 2; mi++) {
                int gr = t0 + wq*32 + mi*16 + qrow_f;
                #pragma unroll
                for (int ni = 0; ni < 4; ni++) {
                    md[mi][ni][0] = *(const uchar2*)&g_mdx[mb + (size_t)gr * TT + gcb + ni*8];
                    md[mi][ni][1] = *(const uchar2*)&g_mdx[mb + (size_t)(gr+8) * TT + gcb + ni*8];
                }
            }
        }

        float sacc[2][4][4];
        #pragma unroll
        for (int mi = 0; mi < 2; mi++)
            #pragma unroll
            for (int i = 0; i < 4; i++)
                #pragma unroll
                for (int j = 0; j < 4; j++) sacc[mi][i][j] = 0.0f;

        #pragma unroll
        for (int ks = 0; ks < 2; ks++) {
            int kb = ks * 16;
            unsigned ah[2][4], al[2][4], bhf[2][4], blf[2][4];
            #pragma unroll
            for (int mi = 0; mi < 2; mi++) {
                int row = wq*32 + mi*16 + (lane & 15);
                unsigned ad = smb + AT_QHI + row*80 + (kb + ((lane >> 4) << 3)) * 2;
                ldsm4(ah[mi], ad);
                ldsm4(al[mi], ad + (AT_QLO - AT_QHI));
            }
            #pragma unroll
            for (int gi = 0; gi < 2; gi++) {
                int nrow = ws*32 + gi*16 + (lane & 7) + ((lane >> 4) & 1) * 8;
                unsigned bd = smb + gb + 0 + nrow*80 + (kb + (((lane >> 3) & 1) << 3)) * 2;
                ldsm4(bhf[gi], bd);
                ldsm4(blf[gi], bd + 5120);
            }
            #pragma unroll
            for (int mi = 0; mi < 2; mi++) {
                #pragma unroll
                for (int ni = 0; ni < 4; ni++) {
                    int gi = ni >> 1, hf = (ni & 1) * 2;
                    mma16816(sacc[mi][ni], ah[mi], &bhf[gi][hf]);
                    mma16816(sacc[mi][ni], ah[mi], &blf[gi][hf]);
                    mma16816(sacc[mi][ni], al[mi], &bhf[gi][hf]);
                }
            }
        }

        unsigned phi[2][8], plo[2][8];
        #pragma unroll
        for (int mi = 0; mi < 2; mi++) {
            #pragma unroll
            for (int ni = 0; ni < 4; ni++) {
                uchar2 m0 = md[mi][ni][0], m1 = md[mi][ni][1];
                float z0 = (m0.x == 255) ? 0.0f : __expf(sacc[mi][ni][0] + sLUT[m0.x]);
                float z1 = (m0.y == 255) ? 0.0f : __expf(sacc[mi][ni][1] + sLUT[m0.y]);
                float z2 = (m1.x == 255) ? 0.0f : __expf(sacc[mi][ni][2] + sLUT[m1.x]);
                float z3 = (m1.y == 255) ? 0.0f : __expf(sacc[mi][ni][3] + sLUT[m1.y]);
                zs[mi][0] += z0 + z1;
                zs[mi][1] += z2 + z3;
                unsigned p01 = cvt2bf(z1, z0);
                unsigned p23 = cvt2bf(z3, z2);
                phi[mi][ni*2]   = p01;
                phi[mi][ni*2+1] = p23;
                float f0 = __uint_as_float(p01 << 16), f1 = __uint_as_float(p01 & 0xFFFF0000u);
                float f2 = __uint_as_float(p23 << 16), f3 = __uint_as_float(p23 & 0xFFFF0000u);
                plo[mi][ni*2]   = cvt2bf(z1 - f1, z0 - f0);
                plo[mi][ni*2+1] = cvt2bf(z3 - f3, z2 - f2);
            }
        }

        #pragma unroll
        for (int kf = 0; kf < 2; kf++) {
            unsigned vbh[2][4], vbl[2][4];
            #pragma unroll
            for (int gi = 0; gi < 2; gi++) {
                int nrow = gi*16 + (lane & 7) + ((lane >> 4) & 1) * 8;
                int col = ws*32 + kf*16 + (((lane >> 3) & 1) << 3);
                unsigned bd = smb + gb + 10240 + nrow*144 + col*2;
                ldsm4(vbh[gi], bd);
                ldsm4(vbl[gi], bd + 4608);
            }
            #pragma unroll
            for (int mi = 0; mi < 2; mi++) {
                #pragma unroll
                for (int ni = 0; ni < 4; ni++) {
                    int gi = ni >> 1, hf = (ni & 1) * 2;
                    mma16816(oacc[mi][ni], &phi[mi][4*kf], &vbh[gi][hf]);
                    mma16816(oacc[mi][ni], &plo[mi][4*kf], &vbh[gi][hf]);
                    mma16816(oacc[mi][ni], &phi[mi][4*kf], &vbl[gi][hf]);
                }
            }
        }
    }

    cudaTriggerProgrammaticLaunchCompletion();

    #pragma unroll
    for (int mi = 0; mi < 2; mi++) {
        zs[mi][0] += __shfl_xor_sync(0xffffffffu, zs[mi][0], 1);
        zs[mi][0] += __shfl_xor_sync(0xffffffffu, zs[mi][0], 2);
        zs[mi][1] += __shfl_xor_sync(0xffffffffu, zs[mi][1], 1);
        zs[mi][1] += __shfl_xor_sync(0xffffffffu, zs[mi][1], 2);
    }
    __syncthreads();

    float* sO  = (float*)(SM_ + 0);        // [128][34]
    float* sRS = (float*)(SM_ + 18432);    // [128]
    if (ws == 1) {
        #pragma unroll
        for (int mi = 0; mi < 2; mi++) {
            int r = wq*32 + mi*16 + qrow_f;
            if ((lane & 3) == 0) {
                sRS[r]     = zs[mi][0];
                sRS[r + 8] = zs[mi][1];
            }
            #pragma unroll
            for (int ni = 0; ni < 4; ni++) {
                int c = ni*8 + ccol_f;
                *(float2*)&sO[r*34 + c]     = make_float2(oacc[mi][ni][0], oacc[mi][ni][1]);
                *(float2*)&sO[(r+8)*34 + c] = make_float2(oacc[mi][ni][2], oacc[mi][ni][3]);
            }
        }
    }
    __syncthreads();
    if (ws == 0) {
        #pragma unroll
        for (int mi = 0; mi < 2; mi++) {
            int r = wq*32 + mi*16 + qrow_f;
            float inv0 = 1.0f / (zs[mi][0] + sRS[r]     + 1e-5f);
            float inv8 = 1.0f / (zs[mi][1] + sRS[r + 8] + 1e-5f);
            size_t o0 = ((size_t)b * TT + t0 + r)     * DD + h * 32;
            size_t o8 = ((size_t)b * TT + t0 + r + 8) * DD + h * 32;
            #pragma unroll
            for (int ni = 0; ni < 4; ni++) {
                int c = ni*8 + ccol_f;
                float2 p0 = *(const float2*)&sO[r*34 + c];
                float2 p8 = *(const float2*)&sO[(r+8)*34 + c];
                float v0 = (oacc[mi][ni][0] + p0.x) * inv0;
                float v1 = (oacc[mi][ni][1] + p0.y) * inv0;
                float v2 = (oacc[mi][ni][2] + p8.x) * inv8;
                float v3 = (oacc[mi][ni][3] + p8.y) * inv8;
                unsigned h0 = cvt2bf(v1, v0);
                unsigned h8 = cvt2bf(v3, v2);
                float f0 = __uint_as_float(h0 << 16), f1 = __uint_as_float(h0 & 0xFFFF0000u);
                float f2 = __uint_as_float(h8 << 16), f3 = __uint_as_float(h8 & 0xFFFF0000u);
                *(unsigned*)&g_athi[o0 + c] = h0;
                *(unsigned*)&g_atlo[o0 + c] = cvt2bf(v1 - f1, v0 - f0);
                *(unsigned*)&g_athi[o8 + c] = h8;
                *(unsigned*)&g_atlo[o8 + c] = cvt2bf(v3 - f3, v2 - f2);
            }
        }
    }
}

__global__ __launch_bounds__(256) void ln_kernel(const float* __restrict__ a,
                                                 const float* __restrict__ b,
                                                 const float* __restrict__ g,
                                                 const float* __restrict__ be,
                                                 float* __restrict__ out,
                                                 int dosplit)
{
    int w    = (blockIdx.x * 256 + threadIdx.x) >> 5;
    int lane = threadIdx.x & 31;
    const float* ap = a + (size_t)w * 256;
    const float* bp = b + (size_t)w * 256;
    cudaGridDependencySynchronize();
    float v[8]; float s = 0.0f;
    #pragma unroll
    for (int u = 0; u < 8; u++) { v[u] = ap[lane + 32*u] + bp[lane + 32*u]; s += v[u]; }
    #pragma unroll
    for (int off = 16; off; off >>= 1) s += __shfl_xor_sync(0xffffffffu, s, off);
    float mu = s * (1.0f / 256.0f);
    float vs = 0.0f;
    #pragma unroll
    for (int u = 0; u < 8; u++) { float d = v[u] - mu; vs = fmaf(d, d, vs); }
    #pragma unroll
    for (int off = 16; off; off >>= 1) vs += __shfl_xor_sync(0xffffffffu, vs, off);
    float rstd = rsqrtf(vs * (1.0f / 256.0f) + 1e-5f);
    cudaTriggerProgrammaticLaunchCompletion();
    #pragma unroll
    for (int u = 0; u < 8; u++) {
        int col = lane + 32*u;
        float o = (v[u] - mu) * rstd * g[col] + be[col];
        out[(size_t)w * 256 + col] = o;
        if (dosplit) {
            __nv_bfloat16 hh = __float2bfloat16(o);
            g_zhi[(size_t)w * 256 + col] = hh;
            g_zlo[(size_t)w * 256 + col] = __float2bfloat16(o - __bfloat162float(hh));
        }
    }
}

extern "C" void kernel_launch(void* const* d_in, const int* in_sizes, int n_in,
                              void* d_out, int out_size)
{
    const float* x    = (const float*)d_in[0];
    const void*  mask = d_in[1];
    const float* rel  = (const float*)d_in[2];
    const float* pw1  = (const float*)d_in[6];
    const float* pb1  = (const float*)d_in[7];
    const float* pw2  = (const float*)d_in[8];
    const float* pb2  = (const float*)d_in[9];
    const float* bo   = (const float*)d_in[11];
    const float* bfv  = (const float*)d_in[13];
    const float* g1   = (const float*)d_in[14];
    const float* be1  = (const float*)d_in[15];
    const float* g2   = (const float*)d_in[16];
    const float* be2  = (const float*)d_in[17];

    float *qraw, *y, *zz;
    __nv_bfloat16 *xhi, *xlo, *athi, *atlo, *zhi, *zlo;
    cudaGetSymbolAddress((void**)&qraw, g_qraw);
    cudaGetSymbolAddress((void**)&y,    g_y);
    cudaGetSymbolAddress((void**)&zz,   g_zz);
    cudaGetSymbolAddress((void**)&xhi,  g_xhi);
    cudaGetSymbolAddress((void**)&xlo,  g_xlo);
    cudaGetSymbolAddress((void**)&athi, g_athi);
    cudaGetSymbolAddress((void**)&atlo, g_atlo);
    cudaGetSymbolAddress((void**)&zhi,  g_zhi);
    cudaGetSymbolAddress((void**)&zlo,  g_zlo);

    static cudaStream_t s1;
    static cudaEvent_t evFork, evJoin;
    static int inited = 0;
    if (!inited) {
        cudaStreamCreateWithFlags(&s1, cudaStreamNonBlocking);
        cudaEventCreateWithFlags(&evFork, cudaEventDisableTiming);
        cudaEventCreateWithFlags(&evJoin, cudaEventDisableTiming);
        cudaFuncSetAttribute(tcmma, cudaFuncAttributeMaxDynamicSharedMemorySize, MM_SMEM);
        cudaFuncSetAttribute(attn_mma_kernel, cudaFuncAttributeMaxDynamicSharedMemorySize, AT_SMEM);
        inited = 1;
    }

    // fork: branch B (splits + QKV GEMM) on s1, branch A (lut/detect/maskfuse) on 0
    cudaEventRecord(evFork, 0);
    cudaStreamWaitEvent(s1, evFork, 0);

    prep_split<<<2688, 256, 0, s1>>>(x, (const float*)d_in[3], (const float*)d_in[4],
                                     (const float*)d_in[5], (const float*)d_in[10],
                                     (const float*)d_in[12]);
    tcmma<<<dim3(32, 4, 3), 256, MM_SMEM, s1>>>(xhi, xlo, 0, nullptr, qraw, qraw, qraw, 0, 1);

    lut_all<<<8, 256>>>(pw1, pb1, pw2, pb2);
    detect_kernel<<<256, 256>>>((const unsigned*)mask);
    maskfuse_kernel<<<4096, 256>>>(rel, mask);

    cudaEventRecord(evJoin, s1);
    cudaStreamWaitEvent(0, evJoin, 0);

    attn_mma_kernel<<<dim3(8, 32), 256, AT_SMEM>>>();

    // ---- serial tail with PDL on every edge ----
    cudaLaunchAttribute pdlAttr[1];
    pdlAttr[0].id = cudaLaunchAttributeProgrammaticStreamSerialization;
    pdlAttr[0].val.programmaticStreamSerializationAllowed = 1;

    {
        cudaLaunchConfig_t cfg = {};
        cfg.gridDim = dim3(32, 4, 1); cfg.blockDim = dim3(256);
        cfg.dynamicSmemBytes = MM_SMEM; cfg.stream = 0;
        cfg.attrs = pdlAttr; cfg.numAttrs = 1;
        cudaLaunchKernelEx(&cfg, tcmma, (const __nv_bfloat16*)athi, (const __nv_bfloat16*)atlo,
                           3, bo, y, y, y, 0, 0);
    }
    {
        cudaLaunchConfig_t cfg = {};
        cfg.gridDim = dim3(512); cfg.blockDim = dim3(256);
        cfg.dynamicSmemBytes = 0; cfg.stream = 0;
        cfg.attrs = pdlAttr; cfg.numAttrs = 1;
        cudaLaunchKernelEx(&cfg, ln_kernel, (const float*)x, (const float*)y, g1, be1,
                           (float*)zz, 1);
    }
    {
        cudaLaunchConfig_t cfg = {};
        cfg.gridDim = dim3(32, 4, 1); cfg.blockDim = dim3(256);
        cfg.dynamicSmemBytes = MM_SMEM; cfg.stream = 0;
        cfg.attrs = pdlAttr; cfg.numAttrs = 1;
        cudaLaunchKernelEx(&cfg, tcmma, (const __nv_bfloat16*)zhi, (const __nv_bfloat16*)zlo,
                           4, bfv, qraw, qraw, qraw, 1, 0);
    }
    {
        cudaLaunchConfig_t cfg = {};
        cfg.gridDim = dim3(512); cfg.blockDim = dim3(256);
        cfg.dynamicSmemBytes = 0; cfg.stream = 0;
        cfg.attrs = pdlAttr; cfg.numAttrs = 1;
        cudaLaunchKernelEx(&cfg, ln_kernel, (const float*)zz, (const float*)qraw, g2, be2,
                           (float*)d_out, 0);
    }
}

// round 15
// speedup vs baseline: 1.0524x; 1.0524x over previous
#include <cuda_runtime.h>
#include <cuda_bf16.h>

#define BB  4
#define TT  1024
#define DD  256
#define HH  8
#define CC  16
#define BT  (BB*TT)

typedef unsigned long long ull;

__device__ __forceinline__ unsigned smem_u32(const void* p) {
    unsigned a;
    asm("{ .reg .u64 t; cvta.to.shared.u64 t, %1; cvt.u32.u64 %0, t; }" : "=r"(a) : "l"(p));
    return a;
}
__device__ __forceinline__ void ldsm4(unsigned* r, unsigned addr) {
    asm volatile("ldmatrix.sync.aligned.m8n8.x4.shared.b16 {%0,%1,%2,%3}, [%4];"
                 : "=r"(r[0]), "=r"(r[1]), "=r"(r[2]), "=r"(r[3]) : "r"(addr));
}
__device__ __forceinline__ void mma16816(float* c, const unsigned* a, const unsigned* b) {
    asm volatile("mma.sync.aligned.m16n8k16.row.col.f32.bf16.bf16.f32 "
                 "{%0,%1,%2,%3}, {%4,%5,%6,%7}, {%8,%9}, {%0,%1,%2,%3};"
                 : "+f"(c[0]), "+f"(c[1]), "+f"(c[2]), "+f"(c[3])
                 : "r"(a[0]), "r"(a[1]), "r"(a[2]), "r"(a[3]), "r"(b[0]), "r"(b[1]));
}
__device__ __forceinline__ unsigned cvt2bf(float hi, float lo) {
    unsigned r;
    asm("cvt.rn.bf16x2.f32 %0, %1, %2;" : "=r"(r) : "f"(hi), "f"(lo));
    return r;
}
__device__ __forceinline__ void cpa16(unsigned dst, const void* src) {
    asm volatile("cp.async.cg.shared.global [%0], [%1], 16;" :: "r"(dst), "l"(src));
}
#define CPA_COMMIT() asm volatile("cp.async.commit_group;" ::: "memory")
#define CPA_WAIT0()  asm volatile("cp.async.wait_group 0;" ::: "memory")

// ---------------- scratch ----------------
__device__ float g_qraw[BT*DD];          // FFN scratch
__device__ float g_y[BT*DD];
__device__ float g_zz[BT*DD];
__device__ unsigned char g_mdx[BB*TT*TT];   // u8: 255=masked, else idx 0..254
__device__ float g_lutv[HH*256];
__device__ int   g_mask_flags = 0;          // idempotent: same bits OR'd every call
__device__ __nv_bfloat16 g_xhi[BT*DD],  g_xlo[BT*DD];
__device__ __nv_bfloat16 g_athi[BT*DD], g_atlo[BT*DD];
__device__ __nv_bfloat16 g_zhi[BT*DD],  g_zlo[BT*DD];
__device__ __nv_bfloat16 g_whi[5*DD*DD], g_wlo[5*DD*DD];
__device__ __nv_bfloat16 g_vthi[32*HH*BB*TT], g_vtlo[32*HH*BB*TT]; // [bh][32][1024]
__device__ __nv_bfloat16 g_qh2[HH*BB*TT*32], g_ql2[HH*BB*TT*32];   // [bh][t][32]
__device__ __nv_bfloat16 g_kh2[HH*BB*TT*32], g_kl2[HH*BB*TT*32];

// ---------------------------------------------------------------------------
// Merged detect + LUT build. Blocks 0..255: mask dtype sniff (idempotent OR).
// Blocks 256..263: per-head coef + 255-cell LUT.
// ---------------------------------------------------------------------------
__global__ void detlut_kernel(const unsigned* __restrict__ w,
                              const float* __restrict__ pw1, const float* __restrict__ pb1,
                              const float* __restrict__ pw2, const float* __restrict__ pb2)
{
    if (blockIdx.x < 256) {
        int i = blockIdx.x * 256 + threadIdx.x;
        unsigned x = w[i];
        int f = 0;
        if (x == 0x3F800000u)               f = 2;
        else if ((x & 0xFFFFu) == 0x3F80u)  f = 4;
        else if (x > 1u)                    f = 1;
        if (f) atomicOr(&g_mask_flags, f);
        return;
    }
    __shared__ float sc[34];
    int h = blockIdx.x - 256;
    int t = threadIdx.x;
    if (t < 16) {
        float w1 = pw1[h*CC + t], b1 = pb1[h*CC + t], w2 = pw2[h*CC + t];
        float beta, delta, k0add, k1add;
        if (w1 != 0.0f) {
            beta  = 0.495f * w2 * fabsf(w1);
            delta = -b1 / w1;
            k0add = 0.505f * w2 * b1;
            k1add = 0.505f * w2 * w1;
        } else {
            beta = 0.0f; delta = 0.0f;
            k0add = w2 * (0.505f * b1 + 0.495f * fabsf(b1));
            k1add = 0.0f;
        }
        #pragma unroll
        for (int off = 1; off < 16; off <<= 1) {
            k0add += __shfl_xor_sync(0x0000FFFFu, k0add, off);
            k1add += __shfl_xor_sync(0x0000FFFFu, k1add, off);
        }
        sc[2 + t]  = beta;
        sc[18 + t] = delta;
        if (t == 0) {
            sc[0] = pb2[h] + k0add;
            sc[1] = k1add;
        }
    }
    __syncthreads();
    if (t == 255) { g_lutv[h*256 + 255] = 0.0f; return; }
    float m = (t + 0.5f) * (1.0f / 255.0f);
    float v = sc[0] + sc[1] * m;
    #pragma unroll
    for (int c = 0; c < 16; c++)
        v += sc[2 + c] * fabsf(m - sc[18 + c]);
    g_lutv[h*256 + t] = -v;
}

__global__ __launch_bounds__(256) void maskfuse_kernel(const float* __restrict__ rd,
                                                       const void* __restrict__ maskp)
{
    int i = blockIdx.x * 256 + threadIdx.x;
    size_t base = (size_t)i * 4;
    int mf = g_mask_flags;
    int mode = (mf & 4) ? 3 : (mf & 2) ? 2 : (mf & 1) ? 1 : 0;
    float4 d4 = *(const float4*)&rd[base];
    int m0, m1, m2, m3;
    if (mode == 0) {
        int4 m = *(const int4*)((const int*)maskp + base);
        m0 = m.x != 0; m1 = m.y != 0; m2 = m.z != 0; m3 = m.w != 0;
    } else if (mode == 1) {
        uchar4 m = *(const uchar4*)((const unsigned char*)maskp + base);
        m0 = m.x != 0; m1 = m.y != 0; m2 = m.z != 0; m3 = m.w != 0;
    } else if (mode == 2) {
        float4 m = *(const float4*)((const float*)maskp + base);
        m0 = m.x != 0.0f; m1 = m.y != 0.0f; m2 = m.z != 0.0f; m3 = m.w != 0.0f;
    } else {
        ushort4 m = *(const ushort4*)((const unsigned short*)maskp + base);
        m0 = m.x != 0; m1 = m.y != 0; m2 = m.z != 0; m3 = m.w != 0;
    }
    int i0 = min(max(__float2int_rd(d4.x * 255.0f), 0), 254);
    int i1 = min(max(__float2int_rd(d4.y * 255.0f), 0), 254);
    int i2 = min(max(__float2int_rd(d4.z * 255.0f), 0), 254);
    int i3 = min(max(__float2int_rd(d4.w * 255.0f), 0), 254);
    uchar4 o;
    o.x = (unsigned char)(m0 ? 255 : i0);
    o.y = (unsigned char)(m1 ? 255 : i1);
    o.z = (unsigned char)(m2 ? 255 : i2);
    o.w = (unsigned char)(m3 ? 255 : i3);
    *(uchar4*)&g_mdx[base] = o;
}

// ---------------------------------------------------------------------------
// Merged split: blocks [0,640) -> weights; blocks [640,2688) -> x.
// ---------------------------------------------------------------------------
__global__ __launch_bounds__(256) void prep_split(const float* __restrict__ x,
                                                  const float* __restrict__ w0,
                                                  const float* __restrict__ w1,
                                                  const float* __restrict__ w2,
                                                  const float* __restrict__ w3,
                                                  const float* __restrict__ w4)
{
    const float* src;
    __nv_bfloat16 *hi, *lo;
    size_t e;
    if (blockIdx.x < 640) {
        int i = blockIdx.x * 256 + threadIdx.x;
        e = (size_t)i * 2;
        int w = (int)(e >> 16);
        size_t off = e & 65535;
        src = ((w == 0) ? w0 : (w == 1) ? w1 : (w == 2) ? w2 : (w == 3) ? w3 : w4) + off - e;
        hi = g_whi; lo = g_wlo;
    } else {
        int i = (blockIdx.x - 640) * 256 + threadIdx.x;
        e = (size_t)i * 2;
        src = x;
        hi = g_xhi; lo = g_xlo;
    }
    float2 v = *(const float2*)&src[e];
    __nv_bfloat16 hx = __float2bfloat16(v.x), hy = __float2bfloat16(v.y);
    __nv_bfloat162 h2; h2.x = hx; h2.y = hy;
    __nv_bfloat162 l2;
    l2.x = __float2bfloat16(v.x - __bfloat162float(hx));
    l2.y = __float2bfloat16(v.y - __bfloat162float(hy));
    *(__nv_bfloat162*)&hi[e] = h2;
    *(__nv_bfloat162*)&lo[e] = l2;
}

// ---------------------------------------------------------------------------
// HMMA GEMM (bf16x3), cp.async double-buffered.
// qkv=1: z<2 -> fused L2-norm + split to q/k layout; z==2 -> fused transpose
// + split to V^T layout (smem transpose). else: fp32 out (+bias)(+lrelu).
// ---------------------------------------------------------------------------
#define MM_AHI 0
#define MM_ALO 18432
#define MM_WHI 36864
#define MM_WLO 46080
#define MM_BUF 55296
#define MM_SMEM (2*MM_BUF)

__global__ __launch_bounds__(256) void tcmma(const __nv_bfloat16* __restrict__ Ahi,
                                             const __nv_bfloat16* __restrict__ Alo,
                                             int widx0,
                                             const float* __restrict__ bias,
                                             float* __restrict__ C0,
                                             float* __restrict__ C1,
                                             float* __restrict__ C2,
                                             int act, int qkv)
{
    extern __shared__ char sm[];
    unsigned smb = smem_u32(sm);
    int tid = threadIdx.x;
    int lane = tid & 31;
    int wid = tid >> 5;
    int wm = wid & 3;
    int wn = wid >> 2;
    int m0 = blockIdx.x * 128, n0 = blockIdx.y * 64;
    int z = blockIdx.z;
    const __nv_bfloat16* Whi = g_whi + (size_t)(widx0 + z) * (DD*DD);
    const __nv_bfloat16* Wlo = g_wlo + (size_t)(widx0 + z) * (DD*DD);
    float* C = (z == 0) ? C0 : (z == 1) ? C1 : C2;

    auto stage = [&](int kc, unsigned bo) {
        #pragma unroll
        for (int it = 0; it < 4; it++) {
            int v = tid + it * 256;
            int row = v >> 3, cg = (v & 7) * 8;
            size_t gofs = (size_t)(m0 + row) * 256 + kc * 64 + cg;
            cpa16(smb + bo + MM_AHI + row*144 + cg*2, &Ahi[gofs]);
            cpa16(smb + bo + MM_ALO + row*144 + cg*2, &Alo[gofs]);
        }
        #pragma unroll
        for (int it = 0; it < 2; it++) {
            int v = tid + it * 256;
            int row = v >> 3, cg = (v & 7) * 8;
            size_t gofs = (size_t)(n0 + row) * 256 + kc * 64 + cg;
            cpa16(smb + bo + MM_WHI + row*144 + cg*2, &Whi[gofs]);
            cpa16(smb + bo + MM_WLO + row*144 + cg*2, &Wlo[gofs]);
        }
    };

    float acc[2][4][4];
    #pragma unroll
    for (int a = 0; a < 2; a++)
        #pragma unroll
        for (int b = 0; b < 4; b++)
            #pragma unroll
            for (int c = 0; c < 4; c++) acc[a][b][c] = 0.0f;

    stage(0, 0);
    CPA_COMMIT();

    for (int kc = 0; kc < 4; kc++) {
        CPA_WAIT0();
        __syncthreads();
        unsigned bo = (unsigned)(kc & 1) * MM_BUF;
        if (kc < 3) { stage(kc + 1, bo ^ MM_BUF); CPA_COMMIT(); }

        #pragma unroll
        for (int ks = 0; ks < 4; ks++) {
            int kb = ks * 16;
            unsigned ah[2][4], al[2][4], bh[2][4], bl[2][4];
            #pragma unroll
            for (int mi = 0; mi < 2; mi++) {
                int row = wm*32 + mi*16 + (lane & 15);
                unsigned ad = smb + bo + MM_AHI + row*144 + (kb + ((lane >> 4) << 3)) * 2;
                ldsm4(ah[mi], ad);
                ldsm4(al[mi], ad + (MM_ALO - MM_AHI));
            }
            #pragma unroll
            for (int gi = 0; gi < 2; gi++) {
                int nrow = wn*32 + gi*16 + (lane & 7) + ((lane >> 4) & 1) * 8;
                unsigned bd = smb + bo + MM_WHI + nrow*144 + (kb + (((lane >> 3) & 1) << 3)) * 2;
                ldsm4(bh[gi], bd);
                ldsm4(bl[gi], bd + (MM_WLO - MM_WHI));
            }
            #pragma unroll
            for (int mi = 0; mi < 2; mi++) {
                #pragma unroll
                for (int ni = 0; ni < 4; ni++) {
                    int gi = ni >> 1, hf = (ni & 1) * 2;
                    mma16816(acc[mi][ni], ah[mi], &bh[gi][hf]);
                    mma16816(acc[mi][ni], ah[mi], &bl[gi][hf]);
                    mma16816(acc[mi][ni], al[mi], &bh[gi][hf]);
                }
            }
        }
    }

    if (qkv && z != 2) {
        __nv_bfloat16* dsthi = (z == 0) ? g_qh2 : g_kh2;
        __nv_bfloat16* dstlo = (z == 0) ? g_ql2 : g_kl2;
        int head = blockIdx.y * 2 + wn;
        #pragma unroll
        for (int mi = 0; mi < 2; mi++) {
            #pragma unroll
            for (int rr = 0; rr < 2; rr++) {
                float v[8];
                #pragma unroll
                for (int ni = 0; ni < 4; ni++) {
                    v[ni*2]   = acc[mi][ni][rr*2];
                    v[ni*2+1] = acc[mi][ni][rr*2+1];
                }
                float ss = 0.0f;
                #pragma unroll
                for (int j = 0; j < 8; j++) ss = fmaf(v[j], v[j], ss);
                ss += __shfl_xor_sync(0xffffffffu, ss, 1);
                ss += __shfl_xor_sync(0xffffffffu, ss, 2);
                float inv = 1.0f / fmaxf(sqrtf(ss), 1e-12f);
                int row = m0 + wm*32 + mi*16 + rr*8 + (lane >> 2);
                int b = row >> 10, t = row & 1023;
                size_t base = (((size_t)(b*8 + head)) * 1024 + t) * 32 + (lane & 3) * 2;
                #pragma unroll
                for (int ni = 0; ni < 4; ni++) {
                    float v0 = v[ni*2] * inv, v1 = v[ni*2+1] * inv;
                    unsigned hh = cvt2bf(v1, v0);
                    float f0 = __uint_as_float(hh << 16), f1 = __uint_as_float(hh & 0xFFFF0000u);
                    *(unsigned*)&dsthi[base + ni*8] = hh;
                    *(unsigned*)&dstlo[base + ni*8] = cvt2bf(v1 - f1, v0 - f0);
                }
            }
        }
        return;
    }
    if (qkv) {
        __syncthreads();
        float* sT = (float*)sm;          // [64 cols][132]
        int rbase_l = wm*32 + (lane >> 2);
        int cbase_l = wn*32 + (lane & 3) * 2;
        #pragma unroll
        for (int mi = 0; mi < 2; mi++) {
            #pragma unroll
            for (int ni = 0; ni < 4; ni++) {
                int col = cbase_l + ni*8;
                int row = rbase_l + mi*16;
                sT[(col+0)*132 + row]     = acc[mi][ni][0];
                sT[(col+1)*132 + row]     = acc[mi][ni][1];
                sT[(col+0)*132 + row + 8] = acc[mi][ni][2];
                sT[(col+1)*132 + row + 8] = acc[mi][ni][3];
            }
        }
        __syncthreads();
        int colg = tid >> 2;
        int tr   = (tid & 3) * 32;
        int head = blockIdx.y * 2 + (colg >> 5);
        int c    = colg & 31;
        int b    = m0 >> 10;
        size_t o = (((size_t)(b*8 + head)) * 32 + c) * 1024 + (m0 & 1023) + tr;
        const float* srcp = &sT[colg*132 + tr];
        unsigned hp[16], lp[16];
        #pragma unroll
        for (int j = 0; j < 16; j++) {
            float v0 = srcp[2*j], v1 = srcp[2*j+1];
            unsigned hh = cvt2bf(v1, v0);
            float f0 = __uint_as_float(hh << 16), f1 = __uint_as_float(hh & 0xFFFF0000u);
            hp[j] = hh;
            lp[j] = cvt2bf(v1 - f1, v0 - f0);
        }
        #pragma unroll
        for (int j = 0; j < 4; j++) {
            *(uint4*)&g_vthi[o + j*8] = make_uint4(hp[j*4], hp[j*4+1], hp[j*4+2], hp[j*4+3]);
            *(uint4*)&g_vtlo[o + j*8] = make_uint4(lp[j*4], lp[j*4+1], lp[j*4+2], lp[j*4+3]);
        }
        return;
    }

    int rbase = m0 + wm*32 + (lane >> 2);
    int cbase = n0 + wn*32 + (lane & 3) * 2;
    #pragma unroll
    for (int mi = 0; mi < 2; mi++) {
        #pragma unroll
        for (int ni = 0; ni < 4; ni++) {
            int col = cbase + ni*8;
            float b0 = bias ? bias[col] : 0.0f;
            float b1 = bias ? bias[col + 1] : 0.0f;
            float v0 = acc[mi][ni][0] + b0;
            float v1 = acc[mi][ni][1] + b1;
            float v2 = acc[mi][ni][2] + b0;
            float v3 = acc[mi][ni][3] + b1;
            if (act) {
                v0 = (v0 >= 0.0f) ? v0 : 0.01f * v0;
                v1 = (v1 >= 0.0f) ? v1 : 0.01f * v1;
                v2 = (v2 >= 0.0f) ? v2 : 0.01f * v2;
                v3 = (v3 >= 0.0f) ? v3 : 0.01f * v3;
            }
            int row = rbase + mi*16;
            *(float2*)&C[(size_t)row * 256 + col]       = make_float2(v0, v1);
            *(float2*)&C[(size_t)(row + 8) * 256 + col] = make_float2(v2, v3);
        }
    }
}

// ---------------------------------------------------------------------------
// HMMA attention (unchanged from 145us round)
// ---------------------------------------------------------------------------
#define AT_QHI 0
#define AT_QLO 10240
#define AT_KV  20480
#define AT_KVBUF 19456
#define AT_LUT 59392
#define AT_SMEM 60416

__global__ __launch_bounds__(256) void attn_mma_kernel()
{
    extern __shared__ __align__(16) char SM_[];
    unsigned smb = smem_u32(SM_);
    float* sLUT = (float*)(SM_ + AT_LUT);

    int tid = threadIdx.x;
    int lane = tid & 31;
    int wid = tid >> 5;
    int wq = wid & 3;
    int ws = wid >> 2;
    int bh = blockIdx.y, b = bh >> 3, h = bh & 7;
    int t0 = blockIdx.x << 7;

    auto stageKV = [&](int s0, unsigned gb) {
        int row = tid >> 2, cg = (tid & 3) * 8;
        size_t gofs = (((size_t)bh * TT) + s0 + row) * 32 + cg;
        cpa16(smb + gb + 0     + row*80 + cg*2, &g_kh2[gofs]);
        cpa16(smb + gb + 5120  + row*80 + cg*2, &g_kl2[gofs]);
        int c = tid >> 3, sg = (tid & 7) * 8;
        size_t vofs = ((size_t)bh * 32 + c) * 1024 + s0 + sg;
        cpa16(smb + gb + 10240 + c*144 + sg*2, &g_vthi[vofs]);
        cpa16(smb + gb + 14848 + c*144 + sg*2, &g_vtlo[vofs]);
    };

    if (tid < 256) sLUT[tid] = g_lutv[h*256 + tid];
    #pragma unroll
    for (int r2 = 0; r2 < 2; r2++) {
        int row = (tid >> 2) + r2*64, cg = (tid & 3) * 8;
        size_t gofs = (((size_t)bh * TT) + t0 + row) * 32 + cg;
        *(uint4*)(SM_ + AT_QHI + row*80 + cg*2) = *(const uint4*)&g_qh2[gofs];
        *(uint4*)(SM_ + AT_QLO + row*80 + cg*2) = *(const uint4*)&g_ql2[gofs];
    }
    stageKV(0, AT_KV);
    CPA_COMMIT();

    float oacc[2][4][4];
    #pragma unroll
    for (int mi = 0; mi < 2; mi++)
        #pragma unroll
        for (int i = 0; i < 4; i++)
            #pragma unroll
            for (int j = 0; j < 4; j++) oacc[mi][i][j] = 0.0f;
    float zs[2][2] = {{0.f,0.f},{0.f,0.f}};

    int qrow_f = (lane >> 2);
    int ccol_f = (lane & 3) * 2;

    #pragma unroll 1
    for (int st = 0; st < 16; st++) {
        int s0 = st << 6;
        CPA_WAIT0();
        __syncthreads();
        unsigned gb = AT_KV + (unsigned)(st & 1) * AT_KVBUF;
        if (st < 15) { stageKV(s0 + 64, gb == AT_KV ? AT_KV + AT_KVBUF : AT_KV); CPA_COMMIT(); }

        uchar2 md[2][4][2];
        {
            size_t mb = (size_t)b * TT * TT;
            int gcb = s0 + ws*32 + ccol_f;
            #pragma unroll
            for (int mi = 0; mi < 2; mi++) {
                int gr = t0 + wq*32 + mi*16 + qrow_f;
                #pragma unroll
                for (int ni = 0; ni < 4; ni++) {
                    md[mi][ni][0] = *(const uchar2*)&g_mdx[mb + (size_t)gr * TT + gcb + ni*8];
                    md[mi][ni][1] = *(const uchar2*)&g_mdx[mb + (size_t)(gr+8) * TT + gcb + ni*8];
                }
            }
        }

        float sacc[2][4][4];
        #pragma unroll
        for (int mi = 0; mi < 2; mi++)
            #pragma unroll
            for (int i = 0; i < 4; i++)
                #pragma unroll
                for (int j = 0; j < 4; j++) sacc[mi][i][j] = 0.0f;

        #pragma unroll
        for (int ks = 0; ks < 2; ks++) {
            int kb = ks * 16;
            unsigned ah[2][4], al[2][4], bhf[2][4], blf[2][4];
            #pragma unroll
            for (int mi = 0; mi < 2; mi++) {
                int row = wq*32 + mi*16 + (lane & 15);
                unsigned ad = smb + AT_QHI + row*80 + (kb + ((lane >> 4) << 3)) * 2;
                ldsm4(ah[mi], ad);
                ldsm4(al[mi], ad + (AT_QLO - AT_QHI));
            }
            #pragma unroll
            for (int gi = 0; gi < 2; gi++) {
                int nrow = ws*32 + gi*16 + (lane & 7) + ((lane >> 4) & 1) * 8;
                unsigned bd = smb + gb + 0 + nrow*80 + (kb + (((lane >> 3) & 1) << 3)) * 2;
                ldsm4(bhf[gi], bd);
                ldsm4(blf[gi], bd + 5120);
            }
            #pragma unroll
            for (int mi = 0; mi < 2; mi++) {
                #pragma unroll
                for (int ni = 0; ni < 4; ni++) {
                    int gi = ni >> 1, hf = (ni & 1) * 2;
                    mma16816(sacc[mi][ni], ah[mi], &bhf[gi][hf]);
                    mma16816(sacc[mi][ni], ah[mi], &blf[gi][hf]);
                    mma16816(sacc[mi][ni], al[mi], &bhf[gi][hf]);
                }
            }
        }

        unsigned phi[2][8], plo[2][8];
        #pragma unroll
        for (int mi = 0; mi < 2; mi++) {
            #pragma unroll
            for (int ni = 0; ni < 4; ni++) {
                uchar2 m0 = md[mi][ni][0], m1 = md[mi][ni][1];
                float z0 = (m0.x == 255) ? 0.0f : __expf(sacc[mi][ni][0] + sLUT[m0.x]);
                float z1 = (m0.y == 255) ? 0.0f : __expf(sacc[mi][ni][1] + sLUT[m0.y]);
                float z2 = (m1.x == 255) ? 0.0f : __expf(sacc[mi][ni][2] + sLUT[m1.x]);
                float z3 = (m1.y == 255) ? 0.0f : __expf(sacc[mi][ni][3] + sLUT[m1.y]);
                zs[mi][0] += z0 + z1;
                zs[mi][1] += z2 + z3;
                unsigned p01 = cvt2bf(z1, z0);
                unsigned p23 = cvt2bf(z3, z2);
                phi[mi][ni*2]   = p01;
                phi[mi][ni*2+1] = p23;
                float f0 = __uint_as_float(p01 << 16), f1 = __uint_as_float(p01 & 0xFFFF0000u);
                float f2 = __uint_as_float(p23 << 16), f3 = __uint_as_float(p23 & 0xFFFF0000u);
                plo[mi][ni*2]   = cvt2bf(z1 - f1, z0 - f0);
                plo[mi][ni*2+1] = cvt2bf(z3 - f3, z2 - f2);
            }
        }

        #pragma unroll
        for (int kf = 0; kf < 2; kf++) {
            unsigned vbh[2][4], vbl[2][4];
            #pragma unroll
            for (int gi = 0; gi < 2; gi++) {
                int nrow = gi*16 + (lane & 7) + ((lane >> 4) & 1) * 8;
                int col = ws*32 + kf*16 + (((lane >> 3) & 1) << 3);
                unsigned bd = smb + gb + 10240 + nrow*144 + col*2;
                ldsm4(vbh[gi], bd);
                ldsm4(vbl[gi], bd + 4608);
            }
            #pragma unroll
            for (int mi = 0; mi < 2; mi++) {
                #pragma unroll
                for (int ni = 0; ni < 4; ni++) {
                    int gi = ni >> 1, hf = (ni & 1) * 2;
                    mma16816(oacc[mi][ni], &phi[mi][4*kf], &vbh[gi][hf]);
                    mma16816(oacc[mi][ni], &plo[mi][4*kf], &vbh[gi][hf]);
                    mma16816(oacc[mi][ni], &phi[mi][4*kf], &vbl[gi][hf]);
                }
            }
        }
    }

    #pragma unroll
    for (int mi = 0; mi < 2; mi++) {
        zs[mi][0] += __shfl_xor_sync(0xffffffffu, zs[mi][0], 1);
        zs[mi][0] += __shfl_xor_sync(0xffffffffu, zs[mi][0], 2);
        zs[mi][1] += __shfl_xor_sync(0xffffffffu, zs[mi][1], 1);
        zs[mi][1] += __shfl_xor_sync(0xffffffffu, zs[mi][1], 2);
    }
    __syncthreads();

    float* sO  = (float*)(SM_ + 0);        // [128][34]
    float* sRS = (float*)(SM_ + 18432);    // [128]
    if (ws == 1) {
        #pragma unroll
        for (int mi = 0; mi < 2; mi++) {
            int r = wq*32 + mi*16 + qrow_f;
            if ((lane & 3) == 0) {
                sRS[r]     = zs[mi][0];
                sRS[r + 8] = zs[mi][1];
            }
            #pragma unroll
            for (int ni = 0; ni < 4; ni++) {
                int c = ni*8 + ccol_f;
                *(float2*)&sO[r*34 + c]     = make_float2(oacc[mi][ni][0], oacc[mi][ni][1]);
                *(float2*)&sO[(r+8)*34 + c] = make_float2(oacc[mi][ni][2], oacc[mi][ni][3]);
            }
        }
    }
    __syncthreads();
    if (ws == 0) {
        #pragma unroll
        for (int mi = 0; mi < 2; mi++) {
            int r = wq*32 + mi*16 + qrow_f;
            float inv0 = 1.0f / (zs[mi][0] + sRS[r]     + 1e-5f);
            float inv8 = 1.0f / (zs[mi][1] + sRS[r + 8] + 1e-5f);
            size_t o0 = ((size_t)b * TT + t0 + r)     * DD + h * 32;
            size_t o8 = ((size_t)b * TT + t0 + r + 8) * DD + h * 32;
            #pragma unroll
            for (int ni = 0; ni < 4; ni++) {
                int c = ni*8 + ccol_f;
                float2 p0 = *(const float2*)&sO[r*34 + c];
                float2 p8 = *(const float2*)&sO[(r+8)*34 + c];
                float v0 = (oacc[mi][ni][0] + p0.x) * inv0;
                float v1 = (oacc[mi][ni][1] + p0.y) * inv0;
                float v2 = (oacc[mi][ni][2] + p8.x) * inv8;
                float v3 = (oacc[mi][ni][3] + p8.y) * inv8;
                unsigned h0 = cvt2bf(v1, v0);
                unsigned h8 = cvt2bf(v3, v2);
                float f0 = __uint_as_float(h0 << 16), f1 = __uint_as_float(h0 & 0xFFFF0000u);
                float f2 = __uint_as_float(h8 << 16), f3 = __uint_as_float(h8 & 0xFFFF0000u);
                *(unsigned*)&g_athi[o0 + c] = h0;
                *(unsigned*)&g_atlo[o0 + c] = cvt2bf(v1 - f1, v0 - f0);
                *(unsigned*)&g_athi[o8 + c] = h8;
                *(unsigned*)&g_atlo[o8 + c] = cvt2bf(v3 - f3, v2 - f2);
            }
        }
    }
}

__global__ __launch_bounds__(256) void ln_kernel(const float* __restrict__ a,
                                                 const float* __restrict__ b,
                                                 const float* __restrict__ g,
                                                 const float* __restrict__ be,
                                                 float* __restrict__ out,
                                                 int dosplit)
{
    int w    = (blockIdx.x * 256 + threadIdx.x) >> 5;
    int lane = threadIdx.x & 31;
    const float* ap = a + (size_t)w * 256;
    const float* bp = b + (size_t)w * 256;
    float v[8]; float s = 0.0f;
    #pragma unroll
    for (int u = 0; u < 8; u++) { v[u] = ap[lane + 32*u] + bp[lane + 32*u]; s += v[u]; }
    #pragma unroll
    for (int off = 16; off; off >>= 1) s += __shfl_xor_sync(0xffffffffu, s, off);
    float mu = s * (1.0f / 256.0f);
    float vs = 0.0f;
    #pragma unroll
    for (int u = 0; u < 8; u++) { float d = v[u] - mu; vs = fmaf(d, d, vs); }
    #pragma unroll
    for (int off = 16; off; off >>= 1) vs += __shfl_xor_sync(0xffffffffu, vs, off);
    float rstd = rsqrtf(vs * (1.0f / 256.0f) + 1e-5f);
    #pragma unroll
    for (int u = 0; u < 8; u++) {
        int col = lane + 32*u;
        float o = (v[u] - mu) * rstd * g[col] + be[col];
        out[(size_t)w * 256 + col] = o;
        if (dosplit) {
            __nv_bfloat16 hh = __float2bfloat16(o);
            g_zhi[(size_t)w * 256 + col] = hh;
            g_zlo[(size_t)w * 256 + col] = __float2bfloat16(o - __bfloat162float(hh));
        }
    }
}

extern "C" void kernel_launch(void* const* d_in, const int* in_sizes, int n_in,
                              void* d_out, int out_size)
{
    const float* x    = (const float*)d_in[0];
    const void*  mask = d_in[1];
    const float* rel  = (const float*)d_in[2];
    const float* pw1  = (const float*)d_in[6];
    const float* pb1  = (const float*)d_in[7];
    const float* pw2  = (const float*)d_in[8];
    const float* pb2  = (const float*)d_in[9];
    const float* bo   = (const float*)d_in[11];
    const float* bfv  = (const float*)d_in[13];
    const float* g1   = (const float*)d_in[14];
    const float* be1  = (const float*)d_in[15];
    const float* g2   = (const float*)d_in[16];
    const float* be2  = (const float*)d_in[17];

    float *qraw, *y, *zz;
    __nv_bfloat16 *xhi, *xlo, *athi, *atlo, *zhi, *zlo;
    cudaGetSymbolAddress((void**)&qraw, g_qraw);
    cudaGetSymbolAddress((void**)&y,    g_y);
    cudaGetSymbolAddress((void**)&zz,   g_zz);
    cudaGetSymbolAddress((void**)&xhi,  g_xhi);
    cudaGetSymbolAddress((void**)&xlo,  g_xlo);
    cudaGetSymbolAddress((void**)&athi, g_athi);
    cudaGetSymbolAddress((void**)&atlo, g_atlo);
    cudaGetSymbolAddress((void**)&zhi,  g_zhi);
    cudaGetSymbolAddress((void**)&zlo,  g_zlo);

    static cudaStream_t s1;
    static cudaEvent_t evFork, evJoin;
    static int inited = 0;
    if (!inited) {
        cudaStreamCreateWithFlags(&s1, cudaStreamNonBlocking);
        cudaEventCreateWithFlags(&evFork, cudaEventDisableTiming);
        cudaEventCreateWithFlags(&evJoin, cudaEventDisableTiming);
        cudaFuncSetAttribute(tcmma, cudaFuncAttributeMaxDynamicSharedMemorySize, MM_SMEM);
        cudaFuncSetAttribute(attn_mma_kernel, cudaFuncAttributeMaxDynamicSharedMemorySize, AT_SMEM);
        inited = 1;
    }

    // fork: branch B (splits + QKV GEMM) on s1, branch A (detlut/maskfuse) on 0
    cudaEventRecord(evFork, 0);
    cudaStreamWaitEvent(s1, evFork, 0);

    prep_split<<<2688, 256, 0, s1>>>(x, (const float*)d_in[3], (const float*)d_in[4],
                                     (const float*)d_in[5], (const float*)d_in[10],
                                     (const float*)d_in[12]);
    tcmma<<<dim3(32, 4, 3), 256, MM_SMEM, s1>>>(xhi, xlo, 0, nullptr, qraw, qraw, qraw, 0, 1);

    detlut_kernel<<<264, 256>>>((const unsigned*)mask, pw1, pb1, pw2, pb2);
    maskfuse_kernel<<<4096, 256>>>(rel, mask);

    cudaEventRecord(evJoin, s1);
    cudaStreamWaitEvent(0, evJoin, 0);

    attn_mma_kernel<<<dim3(8, 32), 256, AT_SMEM>>>();

    tcmma<<<dim3(32, 4, 1), 256, MM_SMEM>>>(athi, atlo, 3, bo, y, y, y, 0, 0);
    ln_kernel<<<512, 256>>>(x, y, g1, be1, zz, 1);
    tcmma<<<dim3(32, 4, 1), 256, MM_SMEM>>>(zhi, zlo, 4, bfv, qraw, qraw, qraw, 1, 0);
    ln_kernel<<<512, 256>>>(zz, qraw, g2, be2, (float*)d_out, 0);
}

// round 16
// speedup vs baseline: 1.0665x; 1.0134x over previous
#include <cuda_runtime.h>
#include <cuda_bf16.h>

#define BB  4
#define TT  1024
#define DD  256
#define HH  8
#define CC  16
#define BT  (BB*TT)

typedef unsigned long long ull;

__device__ __forceinline__ unsigned smem_u32(const void* p) {
    unsigned a;
    asm("{ .reg .u64 t; cvta.to.shared.u64 t, %1; cvt.u32.u64 %0, t; }" : "=r"(a) : "l"(p));
    return a;
}
__device__ __forceinline__ void ldsm4(unsigned* r, unsigned addr) {
    asm volatile("ldmatrix.sync.aligned.m8n8.x4.shared.b16 {%0,%1,%2,%3}, [%4];"
                 : "=r"(r[0]), "=r"(r[1]), "=r"(r[2]), "=r"(r[3]) : "r"(addr));
}
__device__ __forceinline__ void mma16816(float* c, const unsigned* a, const unsigned* b) {
    asm volatile("mma.sync.aligned.m16n8k16.row.col.f32.bf16.bf16.f32 "
                 "{%0,%1,%2,%3}, {%4,%5,%6,%7}, {%8,%9}, {%0,%1,%2,%3};"
                 : "+f"(c[0]), "+f"(c[1]), "+f"(c[2]), "+f"(c[3])
                 : "r"(a[0]), "r"(a[1]), "r"(a[2]), "r"(a[3]), "r"(b[0]), "r"(b[1]));
}
__device__ __forceinline__ unsigned cvt2bf(float hi, float lo) {
    unsigned r;
    asm("cvt.rn.bf16x2.f32 %0, %1, %2;" : "=r"(r) : "f"(hi), "f"(lo));
    return r;
}
__device__ __forceinline__ void cpa16(unsigned dst, const void* src) {
    asm volatile("cp.async.cg.shared.global [%0], [%1], 16;" :: "r"(dst), "l"(src));
}
#define CPA_COMMIT() asm volatile("cp.async.commit_group;" ::: "memory")
#define CPA_WAIT0()  asm volatile("cp.async.wait_group 0;" ::: "memory")

// ---------------- scratch ----------------
__device__ float g_zz[BT*DD];
__device__ unsigned char g_mdx[BB*TT*TT];   // u8: 255=masked, else idx 0..254
__device__ float g_lutv[HH*256];
__device__ int   g_mask_flags = 0;          // idempotent: same bits OR'd every call
__device__ __nv_bfloat16 g_xhi[BT*DD],  g_xlo[BT*DD];
__device__ __nv_bfloat16 g_athi[BT*DD], g_atlo[BT*DD];
__device__ __nv_bfloat16 g_zhi[BT*DD],  g_zlo[BT*DD];
__device__ __nv_bfloat16 g_whi[5*DD*DD], g_wlo[5*DD*DD];
__device__ __nv_bfloat16 g_vthi[32*HH*BB*TT], g_vtlo[32*HH*BB*TT]; // [bh][32][1024]
__device__ __nv_bfloat16 g_qh2[HH*BB*TT*32], g_ql2[HH*BB*TT*32];   // [bh][t][32]
__device__ __nv_bfloat16 g_kh2[HH*BB*TT*32], g_kl2[HH*BB*TT*32];
__device__ float g_qraw[BT*DD];  // scratch for QKV z-output routing

// ---------------------------------------------------------------------------
// Merged detect + LUT build.
// ---------------------------------------------------------------------------
__global__ void detlut_kernel(const unsigned* __restrict__ w,
                              const float* __restrict__ pw1, const float* __restrict__ pb1,
                              const float* __restrict__ pw2, const float* __restrict__ pb2)
{
    if (blockIdx.x < 256) {
        int i = blockIdx.x * 256 + threadIdx.x;
        unsigned x = w[i];
        int f = 0;
        if (x == 0x3F800000u)               f = 2;
        else if ((x & 0xFFFFu) == 0x3F80u)  f = 4;
        else if (x > 1u)                    f = 1;
        if (f) atomicOr(&g_mask_flags, f);
        return;
    }
    __shared__ float sc[34];
    int h = blockIdx.x - 256;
    int t = threadIdx.x;
    if (t < 16) {
        float w1 = pw1[h*CC + t], b1 = pb1[h*CC + t], w2 = pw2[h*CC + t];
        float beta, delta, k0add, k1add;
        if (w1 != 0.0f) {
            beta  = 0.495f * w2 * fabsf(w1);
            delta = -b1 / w1;
            k0add = 0.505f * w2 * b1;
            k1add = 0.505f * w2 * w1;
        } else {
            beta = 0.0f; delta = 0.0f;
            k0add = w2 * (0.505f * b1 + 0.495f * fabsf(b1));
            k1add = 0.0f;
        }
        #pragma unroll
        for (int off = 1; off < 16; off <<= 1) {
            k0add += __shfl_xor_sync(0x0000FFFFu, k0add, off);
            k1add += __shfl_xor_sync(0x0000FFFFu, k1add, off);
        }
        sc[2 + t]  = beta;
        sc[18 + t] = delta;
        if (t == 0) {
            sc[0] = pb2[h] + k0add;
            sc[1] = k1add;
        }
    }
    __syncthreads();
    if (t == 255) { g_lutv[h*256 + 255] = 0.0f; return; }
    float m = (t + 0.5f) * (1.0f / 255.0f);
    float v = sc[0] + sc[1] * m;
    #pragma unroll
    for (int c = 0; c < 16; c++)
        v += sc[2 + c] * fabsf(m - sc[18 + c]);
    g_lutv[h*256 + t] = -v;
}

__global__ __launch_bounds__(256) void maskfuse_kernel(const float* __restrict__ rd,
                                                       const void* __restrict__ maskp)
{
    int i = blockIdx.x * 256 + threadIdx.x;
    size_t base = (size_t)i * 4;
    int mf = g_mask_flags;
    int mode = (mf & 4) ? 3 : (mf & 2) ? 2 : (mf & 1) ? 1 : 0;
    float4 d4 = *(const float4*)&rd[base];
    int m0, m1, m2, m3;
    if (mode == 0) {
        int4 m = *(const int4*)((const int*)maskp + base);
        m0 = m.x != 0; m1 = m.y != 0; m2 = m.z != 0; m3 = m.w != 0;
    } else if (mode == 1) {
        uchar4 m = *(const uchar4*)((const unsigned char*)maskp + base);
        m0 = m.x != 0; m1 = m.y != 0; m2 = m.z != 0; m3 = m.w != 0;
    } else if (mode == 2) {
        float4 m = *(const float4*)((const float*)maskp + base);
        m0 = m.x != 0.0f; m1 = m.y != 0.0f; m2 = m.z != 0.0f; m3 = m.w != 0.0f;
    } else {
        ushort4 m = *(const ushort4*)((const unsigned short*)maskp + base);
        m0 = m.x != 0; m1 = m.y != 0; m2 = m.z != 0; m3 = m.w != 0;
    }
    int i0 = min(max(__float2int_rd(d4.x * 255.0f), 0), 254);
    int i1 = min(max(__float2int_rd(d4.y * 255.0f), 0), 254);
    int i2 = min(max(__float2int_rd(d4.z * 255.0f), 0), 254);
    int i3 = min(max(__float2int_rd(d4.w * 255.0f), 0), 254);
    uchar4 o;
    o.x = (unsigned char)(m0 ? 255 : i0);
    o.y = (unsigned char)(m1 ? 255 : i1);
    o.z = (unsigned char)(m2 ? 255 : i2);
    o.w = (unsigned char)(m3 ? 255 : i3);
    *(uchar4*)&g_mdx[base] = o;
}

__global__ __launch_bounds__(256) void prep_split(const float* __restrict__ x,
                                                  const float* __restrict__ w0,
                                                  const float* __restrict__ w1,
                                                  const float* __restrict__ w2,
                                                  const float* __restrict__ w3,
                                                  const float* __restrict__ w4)
{
    const float* src;
    __nv_bfloat16 *hi, *lo;
    size_t e;
    if (blockIdx.x < 640) {
        int i = blockIdx.x * 256 + threadIdx.x;
        e = (size_t)i * 2;
        int w = (int)(e >> 16);
        size_t off = e & 65535;
        src = ((w == 0) ? w0 : (w == 1) ? w1 : (w == 2) ? w2 : (w == 3) ? w3 : w4) + off - e;
        hi = g_whi; lo = g_wlo;
    } else {
        int i = (blockIdx.x - 640) * 256 + threadIdx.x;
        e = (size_t)i * 2;
        src = x;
        hi = g_xhi; lo = g_xlo;
    }
    float2 v = *(const float2*)&src[e];
    __nv_bfloat16 hx = __float2bfloat16(v.x), hy = __float2bfloat16(v.y);
    __nv_bfloat162 h2; h2.x = hx; h2.y = hy;
    __nv_bfloat162 l2;
    l2.x = __float2bfloat16(v.x - __bfloat162float(hx));
    l2.y = __float2bfloat16(v.y - __bfloat162float(hy));
    *(__nv_bfloat162*)&hi[e] = h2;
    *(__nv_bfloat162*)&lo[e] = l2;
}

// ---------------------------------------------------------------------------
// HMMA GEMM (bf16x3), cp.async double-buffered — QKV flavor only now.
// z<2 -> fused L2-norm + split to q/k layout; z==2 -> fused transpose + split V^T.
// ---------------------------------------------------------------------------
#define MM_AHI 0
#define MM_ALO 18432
#define MM_WHI 36864
#define MM_WLO 46080
#define MM_BUF 55296
#define MM_SMEM (2*MM_BUF)

__global__ __launch_bounds__(256) void tcmma(const __nv_bfloat16* __restrict__ Ahi,
                                             const __nv_bfloat16* __restrict__ Alo,
                                             int widx0,
                                             float* __restrict__ C0)
{
    extern __shared__ char sm[];
    unsigned smb = smem_u32(sm);
    int tid = threadIdx.x;
    int lane = tid & 31;
    int wid = tid >> 5;
    int wm = wid & 3;
    int wn = wid >> 2;
    int m0 = blockIdx.x * 128, n0 = blockIdx.y * 64;
    int z = blockIdx.z;
    const __nv_bfloat16* Whi = g_whi + (size_t)(widx0 + z) * (DD*DD);
    const __nv_bfloat16* Wlo = g_wlo + (size_t)(widx0 + z) * (DD*DD);

    auto stage = [&](int kc, unsigned bo) {
        #pragma unroll
        for (int it = 0; it < 4; it++) {
            int v = tid + it * 256;
            int row = v >> 3, cg = (v & 7) * 8;
            size_t gofs = (size_t)(m0 + row) * 256 + kc * 64 + cg;
            cpa16(smb + bo + MM_AHI + row*144 + cg*2, &Ahi[gofs]);
            cpa16(smb + bo + MM_ALO + row*144 + cg*2, &Alo[gofs]);
        }
        #pragma unroll
        for (int it = 0; it < 2; it++) {
            int v = tid + it * 256;
            int row = v >> 3, cg = (v & 7) * 8;
            size_t gofs = (size_t)(n0 + row) * 256 + kc * 64 + cg;
            cpa16(smb + bo + MM_WHI + row*144 + cg*2, &Whi[gofs]);
            cpa16(smb + bo + MM_WLO + row*144 + cg*2, &Wlo[gofs]);
        }
    };

    float acc[2][4][4];
    #pragma unroll
    for (int a = 0; a < 2; a++)
        #pragma unroll
        for (int b = 0; b < 4; b++)
            #pragma unroll
            for (int c = 0; c < 4; c++) acc[a][b][c] = 0.0f;

    stage(0, 0);
    CPA_COMMIT();

    for (int kc = 0; kc < 4; kc++) {
        CPA_WAIT0();
        __syncthreads();
        unsigned bo = (unsigned)(kc & 1) * MM_BUF;
        if (kc < 3) { stage(kc + 1, bo ^ MM_BUF); CPA_COMMIT(); }

        #pragma unroll
        for (int ks = 0; ks < 4; ks++) {
            int kb = ks * 16;
            unsigned ah[2][4], al[2][4], bh[2][4], bl[2][4];
            #pragma unroll
            for (int mi = 0; mi < 2; mi++) {
                int row = wm*32 + mi*16 + (lane & 15);
                unsigned ad = smb + bo + MM_AHI + row*144 + (kb + ((lane >> 4) << 3)) * 2;
                ldsm4(ah[mi], ad);
                ldsm4(al[mi], ad + (MM_ALO - MM_AHI));
            }
            #pragma unroll
            for (int gi = 0; gi < 2; gi++) {
                int nrow = wn*32 + gi*16 + (lane & 7) + ((lane >> 4) & 1) * 8;
                unsigned bd = smb + bo + MM_WHI + nrow*144 + (kb + (((lane >> 3) & 1) << 3)) * 2;
                ldsm4(bh[gi], bd);
                ldsm4(bl[gi], bd + (MM_WLO - MM_WHI));
            }
            #pragma unroll
            for (int mi = 0; mi < 2; mi++) {
                #pragma unroll
                for (int ni = 0; ni < 4; ni++) {
                    int gi = ni >> 1, hf = (ni & 1) * 2;
                    mma16816(acc[mi][ni], ah[mi], &bh[gi][hf]);
                    mma16816(acc[mi][ni], ah[mi], &bl[gi][hf]);
                    mma16816(acc[mi][ni], al[mi], &bh[gi][hf]);
                }
            }
        }
    }

    if (z != 2) {
        __nv_bfloat16* dsthi = (z == 0) ? g_qh2 : g_kh2;
        __nv_bfloat16* dstlo = (z == 0) ? g_ql2 : g_kl2;
        int head = blockIdx.y * 2 + wn;
        #pragma unroll
        for (int mi = 0; mi < 2; mi++) {
            #pragma unroll
            for (int rr = 0; rr < 2; rr++) {
                float v[8];
                #pragma unroll
                for (int ni = 0; ni < 4; ni++) {
                    v[ni*2]   = acc[mi][ni][rr*2];
                    v[ni*2+1] = acc[mi][ni][rr*2+1];
                }
                float ss = 0.0f;
                #pragma unroll
                for (int j = 0; j < 8; j++) ss = fmaf(v[j], v[j], ss);
                ss += __shfl_xor_sync(0xffffffffu, ss, 1);
                ss += __shfl_xor_sync(0xffffffffu, ss, 2);
                float inv = 1.0f / fmaxf(sqrtf(ss), 1e-12f);
                int row = m0 + wm*32 + mi*16 + rr*8 + (lane >> 2);
                int b = row >> 10, t = row & 1023;
                size_t base = (((size_t)(b*8 + head)) * 1024 + t) * 32 + (lane & 3) * 2;
                #pragma unroll
                for (int ni = 0; ni < 4; ni++) {
                    float v0 = v[ni*2] * inv, v1 = v[ni*2+1] * inv;
                    unsigned hh = cvt2bf(v1, v0);
                    float f0 = __uint_as_float(hh << 16), f1 = __uint_as_float(hh & 0xFFFF0000u);
                    *(unsigned*)&dsthi[base + ni*8] = hh;
                    *(unsigned*)&dstlo[base + ni*8] = cvt2bf(v1 - f1, v0 - f0);
                }
            }
        }
        return;
    }
    // z == 2: V. Transpose via smem, split hi/lo, write [bh][c][t].
    __syncthreads();
    float* sT = (float*)sm;          // [64 cols][132]
    int rbase_l = wm*32 + (lane >> 2);
    int cbase_l = wn*32 + (lane & 3) * 2;
    #pragma unroll
    for (int mi = 0; mi < 2; mi++) {
        #pragma unroll
        for (int ni = 0; ni < 4; ni++) {
            int col = cbase_l + ni*8;
            int row = rbase_l + mi*16;
            sT[(col+0)*132 + row]     = acc[mi][ni][0];
            sT[(col+1)*132 + row]     = acc[mi][ni][1];
            sT[(col+0)*132 + row + 8] = acc[mi][ni][2];
            sT[(col+1)*132 + row + 8] = acc[mi][ni][3];
        }
    }
    __syncthreads();
    int colg = tid >> 2;
    int tr   = (tid & 3) * 32;
    int head = blockIdx.y * 2 + (colg >> 5);
    int c    = colg & 31;
    int b    = m0 >> 10;
    size_t o = (((size_t)(b*8 + head)) * 32 + c) * 1024 + (m0 & 1023) + tr;
    const float* srcp = &sT[colg*132 + tr];
    unsigned hp[16], lp[16];
    #pragma unroll
    for (int j = 0; j < 16; j++) {
        float v0 = srcp[2*j], v1 = srcp[2*j+1];
        unsigned hh = cvt2bf(v1, v0);
        float f0 = __uint_as_float(hh << 16), f1 = __uint_as_float(hh & 0xFFFF0000u);
        hp[j] = hh;
        lp[j] = cvt2bf(v1 - f1, v0 - f0);
    }
    #pragma unroll
    for (int j = 0; j < 4; j++) {
        *(uint4*)&g_vthi[o + j*8] = make_uint4(hp[j*4], hp[j*4+1], hp[j*4+2], hp[j*4+3]);
        *(uint4*)&g_vtlo[o + j*8] = make_uint4(lp[j*4], lp[j*4+1], lp[j*4+2], lp[j*4+3]);
    }
}

// ---------------------------------------------------------------------------
// Full-row GEMM + fused residual LayerNorm (bf16x3).
// M-tile 32, N=256 per CTA (grid 128). 8 warps = 2(M) x 4(N), warp 16x64.
// Epilogue: +bias (+lrelu) -> smem -> +resid -> rowwise LN -> outf (+ hi/lo split).
// smem buffer: AHI 0 (4608) | ALO 4608 | WHI 9216 (36864) | WLO 46080 | BUF 82944
// ---------------------------------------------------------------------------
#define FL_AHI 0
#define FL_ALO 4608
#define FL_WHI 9216
#define FL_WLO 46080
#define FL_BUF 82944
#define FL_SMEM (2*FL_BUF)

__global__ __launch_bounds__(256) void tcmma_ln(const __nv_bfloat16* __restrict__ Ahi,
                                                const __nv_bfloat16* __restrict__ Alo,
                                                int widx,
                                                const float* __restrict__ bias,
                                                const float* __restrict__ resid,
                                                const float* __restrict__ gam,
                                                const float* __restrict__ bet,
                                                float* __restrict__ outf,
                                                __nv_bfloat16* __restrict__ outhi,
                                                __nv_bfloat16* __restrict__ outlo,
                                                int act)
{
    extern __shared__ char sm[];
    unsigned smb = smem_u32(sm);
    int tid = threadIdx.x;
    int lane = tid & 31;
    int wid = tid >> 5;
    int wm = wid >> 2;     // 0..1 (16 rows each)
    int wn = wid & 3;      // 0..3 (64 cols each)
    int m0 = blockIdx.x * 32;
    const __nv_bfloat16* Whi = g_whi + (size_t)widx * (DD*DD);
    const __nv_bfloat16* Wlo = g_wlo + (size_t)widx * (DD*DD);

    auto stage = [&](int kc, unsigned bo) {
        {   // A: 32 rows x 64 cols, hi+lo (1 iter each)
            int row = tid >> 3, cg = (tid & 7) * 8;
            size_t gofs = (size_t)(m0 + row) * 256 + kc * 64 + cg;
            cpa16(smb + bo + FL_AHI + row*144 + cg*2, &Ahi[gofs]);
            cpa16(smb + bo + FL_ALO + row*144 + cg*2, &Alo[gofs]);
        }
        #pragma unroll
        for (int it = 0; it < 8; it++) {   // W: 256 rows x 64 cols, hi+lo
            int v = tid + it * 256;
            int row = v >> 3, cg = (v & 7) * 8;
            size_t gofs = (size_t)row * 256 + kc * 64 + cg;
            cpa16(smb + bo + FL_WHI + row*144 + cg*2, &Whi[gofs]);
            cpa16(smb + bo + FL_WLO + row*144 + cg*2, &Wlo[gofs]);
        }
    };

    float acc[8][4];
    #pragma unroll
    for (int i = 0; i < 8; i++)
        #pragma unroll
        for (int j = 0; j < 4; j++) acc[i][j] = 0.0f;

    stage(0, 0);
    CPA_COMMIT();

    for (int kc = 0; kc < 4; kc++) {
        CPA_WAIT0();
        __syncthreads();
        unsigned bo = (unsigned)(kc & 1) * FL_BUF;
        if (kc < 3) { stage(kc + 1, bo ^ FL_BUF); CPA_COMMIT(); }

        #pragma unroll
        for (int ks = 0; ks < 4; ks++) {
            int kb = ks * 16;
            unsigned ah[4], al[4], bh[4][4], bl[4][4];
            {
                int row = wm*16 + (lane & 15);
                unsigned ad = smb + bo + FL_AHI + row*144 + (kb + ((lane >> 4) << 3)) * 2;
                ldsm4(ah, ad);
                ldsm4(al, ad + (FL_ALO - FL_AHI));
            }
            #pragma unroll
            for (int gi = 0; gi < 4; gi++) {
                int nrow = wn*64 + gi*16 + (lane & 7) + ((lane >> 4) & 1) * 8;
                unsigned bd = smb + bo + FL_WHI + nrow*144 + (kb + (((lane >> 3) & 1) << 3)) * 2;
                ldsm4(bh[gi], bd);
                ldsm4(bl[gi], bd + (FL_WLO - FL_WHI));
            }
            #pragma unroll
            for (int ni = 0; ni < 8; ni++) {
                int gi = ni >> 1, hf = (ni & 1) * 2;
                mma16816(acc[ni], ah, &bh[gi][hf]);
                mma16816(acc[ni], ah, &bl[gi][hf]);
                mma16816(acc[ni], al, &bh[gi][hf]);
            }
        }
    }

    // ---- epilogue: bias(+act) -> sO, then fused residual LN ----
    __syncthreads();
    float* sO = (float*)sm;    // [32][260]
    int rb = wm*16 + (lane >> 2);
    int cb = wn*64 + (lane & 3) * 2;
    #pragma unroll
    for (int ni = 0; ni < 8; ni++) {
        int col = cb + ni*8;
        float b0 = bias[col], b1 = bias[col + 1];
        float v0 = acc[ni][0] + b0;
        float v1 = acc[ni][1] + b1;
        float v2 = acc[ni][2] + b0;
        float v3 = acc[ni][3] + b1;
        if (act) {
            v0 = (v0 >= 0.0f) ? v0 : 0.01f * v0;
            v1 = (v1 >= 0.0f) ? v1 : 0.01f * v1;
            v2 = (v2 >= 0.0f) ? v2 : 0.01f * v2;
            v3 = (v3 >= 0.0f) ? v3 : 0.01f * v3;
        }
        sO[rb*260 + col]       = v0;
        sO[rb*260 + col + 1]   = v1;
        sO[(rb+8)*260 + col]     = v2;
        sO[(rb+8)*260 + col + 1] = v3;
    }
    __syncthreads();

    // LN: each warp handles 4 rows (8 warps x 4 = 32)
    #pragma unroll
    for (int rr = 0; rr < 4; rr++) {
        int r = wid*4 + rr;
        int grow = m0 + r;
        const float* rp = resid + (size_t)grow * 256;
        float v[8]; float s = 0.0f;
        #pragma unroll
        for (int u = 0; u < 8; u++) {
            int col = lane + 32*u;
            v[u] = rp[col] + sO[r*260 + col];
            s += v[u];
        }
        #pragma unroll
        for (int off = 16; off; off >>= 1) s += __shfl_xor_sync(0xffffffffu, s, off);
        float mu = s * (1.0f / 256.0f);
        float vs = 0.0f;
        #pragma unroll
        for (int u = 0; u < 8; u++) { float d = v[u] - mu; vs = fmaf(d, d, vs); }
        #pragma unroll
        for (int off = 16; off; off >>= 1) vs += __shfl_xor_sync(0xffffffffu, vs, off);
        float rstd = rsqrtf(vs * (1.0f / 256.0f) + 1e-5f);
        #pragma unroll
        for (int u = 0; u < 8; u++) {
            int col = lane + 32*u;
            float o = (v[u] - mu) * rstd * gam[col] + bet[col];
            outf[(size_t)grow * 256 + col] = o;
            if (outhi) {
                __nv_bfloat16 hh = __float2bfloat16(o);
                outhi[(size_t)grow * 256 + col] = hh;
                outlo[(size_t)grow * 256 + col] = __float2bfloat16(o - __bfloat162float(hh));
            }
        }
    }
}

// ---------------------------------------------------------------------------
// HMMA attention (unchanged)
// ---------------------------------------------------------------------------
#define AT_QHI 0
#define AT_QLO 10240
#define AT_KV  20480
#define AT_KVBUF 19456
#define AT_LUT 59392
#define AT_SMEM 60416

__global__ __launch_bounds__(256) void attn_mma_kernel()
{
    extern __shared__ __align__(16) char SM_[];
    unsigned smb = smem_u32(SM_);
    float* sLUT = (float*)(SM_ + AT_LUT);

    int tid = threadIdx.x;
    int lane = tid & 31;
    int wid = tid >> 5;
    int wq = wid & 3;
    int ws = wid >> 2;
    int bh = blockIdx.y, b = bh >> 3, h = bh & 7;
    int t0 = blockIdx.x << 7;

    auto stageKV = [&](int s0, unsigned gb) {
        int row = tid >> 2, cg = (tid & 3) * 8;
        size_t gofs = (((size_t)bh * TT) + s0 + row) * 32 + cg;
        cpa16(smb + gb + 0     + row*80 + cg*2, &g_kh2[gofs]);
        cpa16(smb + gb + 5120  + row*80 + cg*2, &g_kl2[gofs]);
        int c = tid >> 3, sg = (tid & 7) * 8;
        size_t vofs = ((size_t)bh * 32 + c) * 1024 + s0 + sg;
        cpa16(smb + gb + 10240 + c*144 + sg*2, &g_vthi[vofs]);
        cpa16(smb + gb + 14848 + c*144 + sg*2, &g_vtlo[vofs]);
    };

    if (tid < 256) sLUT[tid] = g_lutv[h*256 + tid];
    #pragma unroll
    for (int r2 = 0; r2 < 2; r2++) {
        int row = (tid >> 2) + r2*64, cg = (tid & 3) * 8;
        size_t gofs = (((size_t)bh * TT) + t0 + row) * 32 + cg;
        *(uint4*)(SM_ + AT_QHI + row*80 + cg*2) = *(const uint4*)&g_qh2[gofs];
        *(uint4*)(SM_ + AT_QLO + row*80 + cg*2) = *(const uint4*)&g_ql2[gofs];
    }
    stageKV(0, AT_KV);
    CPA_COMMIT();

    float oacc[2][4][4];
    #pragma unroll
    for (int mi = 0; mi < 2; mi++)
        #pragma unroll
        for (int i = 0; i < 4; i++)
            #pragma unroll
            for (int j = 0; j < 4; j++) oacc[mi][i][j] = 0.0f;
    float zs[2][2] = {{0.f,0.f},{0.f,0.f}};

    int qrow_f = (lane >> 2);
    int ccol_f = (lane & 3) * 2;

    #pragma unroll 1
    for (int st = 0; st < 16; st++) {
        int s0 = st << 6;
        CPA_WAIT0();
        __syncthreads();
        unsigned gb = AT_KV + (unsigned)(st & 1) * AT_KVBUF;
        if (st < 15) { stageKV(s0 + 64, gb == AT_KV ? AT_KV + AT_KVBUF : AT_KV); CPA_COMMIT(); }

        uchar2 md[2][4][2];
        {
            size_t mb = (size_t)b * TT * TT;
            int gcb = s0 + ws*32 + ccol_f;
            #pragma unroll
            for (int mi = 0; mi < 2; mi++) {
                int gr = t0 + wq*32 + mi*16 + qrow_f;
                #pragma unroll
                for (int ni = 0; ni < 4; ni++) {
                    md[mi][ni][0] = *(const uchar2*)&g_mdx[mb + (size_t)gr * TT + gcb + ni*8];
                    md[mi][ni][1] = *(const uchar2*)&g_mdx[mb + (size_t)(gr+8) * TT + gcb + ni*8];
                }
            }
        }

        float sacc[2][4][4];
        #pragma unroll
        for (int mi = 0; mi < 2; mi++)
            #pragma unroll
            for (int i = 0; i < 4; i++)
                #pragma unroll
                for (int j = 0; j < 4; j++) sacc[mi][i][j] = 0.0f;

        #pragma unroll
        for (int ks = 0; ks < 2; ks++) {
            int kb = ks * 16;
            unsigned ah[2][4], al[2][4], bhf[2][4], blf[2][4];
            #pragma unroll
            for (int mi = 0; mi < 2; mi++) {
                int row = wq*32 + mi*16 + (lane & 15);
                unsigned ad = smb + AT_QHI + row*80 + (kb + ((lane >> 4) << 3)) * 2;
                ldsm4(ah[mi], ad);
                ldsm4(al[mi], ad + (AT_QLO - AT_QHI));
            }
            #pragma unroll
            for (int gi = 0; gi < 2; gi++) {
                int nrow = ws*32 + gi*16 + (lane & 7) + ((lane >> 4) & 1) * 8;
                unsigned bd = smb + gb + 0 + nrow*80 + (kb + (((lane >> 3) & 1) << 3)) * 2;
                ldsm4(bhf[gi], bd);
                ldsm4(blf[gi], bd + 5120);
            }
            #pragma unroll
            for (int mi = 0; mi < 2; mi++) {
                #pragma unroll
                for (int ni = 0; ni < 4; ni++) {
                    int gi = ni >> 1, hf = (ni & 1) * 2;
                    mma16816(sacc[mi][ni], ah[mi], &bhf[gi][hf]);
                    mma16816(sacc[mi][ni], ah[mi], &blf[gi][hf]);
                    mma16816(sacc[mi][ni], al[mi], &bhf[gi][hf]);
                }
            }
        }

        unsigned phi[2][8], plo[2][8];
        #pragma unroll
        for (int mi = 0; mi < 2; mi++) {
            #pragma unroll
            for (int ni = 0; ni < 4; ni++) {
                uchar2 m0 = md[mi][ni][0], m1 = md[mi][ni][1];
                float z0 = (m0.x == 255) ? 0.0f : __expf(sacc[mi][ni][0] + sLUT[m0.x]);
                float z1 = (m0.y == 255) ? 0.0f : __expf(sacc[mi][ni][1] + sLUT[m0.y]);
                float z2 = (m1.x == 255) ? 0.0f : __expf(sacc[mi][ni][2] + sLUT[m1.x]);
                float z3 = (m1.y == 255) ? 0.0f : __expf(sacc[mi][ni][3] + sLUT[m1.y]);
                zs[mi][0] += z0 + z1;
                zs[mi][1] += z2 + z3;
                unsigned p01 = cvt2bf(z1, z0);
                unsigned p23 = cvt2bf(z3, z2);
                phi[mi][ni*2]   = p01;
                phi[mi][ni*2+1] = p23;
                float f0 = __uint_as_float(p01 << 16), f1 = __uint_as_float(p01 & 0xFFFF0000u);
                float f2 = __uint_as_float(p23 << 16), f3 = __uint_as_float(p23 & 0xFFFF0000u);
                plo[mi][ni*2]   = cvt2bf(z1 - f1, z0 - f0);
                plo[mi][ni*2+1] = cvt2bf(z3 - f3, z2 - f2);
            }
        }

        #pragma unroll
        for (int kf = 0; kf < 2; kf++) {
            unsigned vbh[2][4], vbl[2][4];
            #pragma unroll
            for (int gi = 0; gi < 2; gi++) {
                int nrow = gi*16 + (lane & 7) + ((lane >> 4) & 1) * 8;
                int col = ws*32 + kf*16 + (((lane >> 3) & 1) << 3);
                unsigned bd = smb + gb + 10240 + nrow*144 + col*2;
                ldsm4(vbh[gi], bd);
                ldsm4(vbl[gi], bd + 4608);
            }
            #pragma unroll
            for (int mi = 0; mi < 2; mi++) {
                #pragma unroll
                for (int ni = 0; ni < 4; ni++) {
                    int gi = ni >> 1, hf = (ni & 1) * 2;
                    mma16816(oacc[mi][ni], &phi[mi][4*kf], &vbh[gi][hf]);
                    mma16816(oacc[mi][ni], &plo[mi][4*kf], &vbh[gi][hf]);
                    mma16816(oacc[mi][ni], &phi[mi][4*kf], &vbl[gi][hf]);
                }
            }
        }
    }

    #pragma unroll
    for (int mi = 0; mi < 2; mi++) {
        zs[mi][0] += __shfl_xor_sync(0xffffffffu, zs[mi][0], 1);
        zs[mi][0] += __shfl_xor_sync(0xffffffffu, zs[mi][0], 2);
        zs[mi][1] += __shfl_xor_sync(0xffffffffu, zs[mi][1], 1);
        zs[mi][1] += __shfl_xor_sync(0xffffffffu, zs[mi][1], 2);
    }
    __syncthreads();

    float* sO  = (float*)(SM_ + 0);        // [128][34]
    float* sRS = (float*)(SM_ + 18432);    // [128]
    if (ws == 1) {
        #pragma unroll
        for (int mi = 0; mi < 2; mi++) {
            int r = wq*32 + mi*16 + qrow_f;
            if ((lane & 3) == 0) {
                sRS[r]     = zs[mi][0];
                sRS[r + 8] = zs[mi][1];
            }
            #pragma unroll
            for (int ni = 0; ni < 4; ni++) {
                int c = ni*8 + ccol_f;
                *(float2*)&sO[r*34 + c]     = make_float2(oacc[mi][ni][0], oacc[mi][ni][1]);
                *(float2*)&sO[(r+8)*34 + c] = make_float2(oacc[mi][ni][2], oacc[mi][ni][3]);
            }
        }
    }
    __syncthreads();
    if (ws == 0) {
        #pragma unroll
        for (int mi = 0; mi < 2; mi++) {
            int r = wq*32 + mi*16 + qrow_f;
            float inv0 = 1.0f / (zs[mi][0] + sRS[r]     + 1e-5f);
            float inv8 = 1.0f / (zs[mi][1] + sRS[r + 8] + 1e-5f);
            size_t o0 = ((size_t)b * TT + t0 + r)     * DD + h * 32;
            size_t o8 = ((size_t)b * TT + t0 + r + 8) * DD + h * 32;
            #pragma unroll
            for (int ni = 0; ni < 4; ni++) {
                int c = ni*8 + ccol_f;
                float2 p0 = *(const float2*)&sO[r*34 + c];
                float2 p8 = *(const float2*)&sO[(r+8)*34 + c];
                float v0 = (oacc[mi][ni][0] + p0.x) * inv0;
                float v1 = (oacc[mi][ni][1] + p0.y) * inv0;
                float v2 = (oacc[mi][ni][2] + p8.x) * inv8;
                float v3 = (oacc[mi][ni][3] + p8.y) * inv8;
                unsigned h0 = cvt2bf(v1, v0);
                unsigned h8 = cvt2bf(v3, v2);
                float f0 = __uint_as_float(h0 << 16), f1 = __uint_as_float(h0 & 0xFFFF0000u);
                float f2 = __uint_as_float(h8 << 16), f3 = __uint_as_float(h8 & 0xFFFF0000u);
                *(unsigned*)&g_athi[o0 + c] = h0;
                *(unsigned*)&g_atlo[o0 + c] = cvt2bf(v1 - f1, v0 - f0);
                *(unsigned*)&g_athi[o8 + c] = h8;
                *(unsigned*)&g_atlo[o8 + c] = cvt2bf(v3 - f3, v2 - f2);
            }
        }
    }
}

extern "C" void kernel_launch(void* const* d_in, const int* in_sizes, int n_in,
                              void* d_out, int out_size)
{
    const float* x    = (const float*)d_in[0];
    const void*  mask = d_in[1];
    const float* rel  = (const float*)d_in[2];
    const float* pw1  = (const float*)d_in[6];
    const float* pb1  = (const float*)d_in[7];
    const float* pw2  = (const float*)d_in[8];
    const float* pb2  = (const float*)d_in[9];
    const float* bo   = (const float*)d_in[11];
    const float* bfv  = (const float*)d_in[13];
    const float* g1   = (const float*)d_in[14];
    const float* be1  = (const float*)d_in[15];
    const float* g2   = (const float*)d_in[16];
    const float* be2  = (const float*)d_in[17];

    float *zz, *qraw;
    __nv_bfloat16 *xhi, *xlo, *athi, *atlo, *zhi, *zlo;
    cudaGetSymbolAddress((void**)&zz,   g_zz);
    cudaGetSymbolAddress((void**)&qraw, g_qraw);
    cudaGetSymbolAddress((void**)&xhi,  g_xhi);
    cudaGetSymbolAddress((void**)&xlo,  g_xlo);
    cudaGetSymbolAddress((void**)&athi, g_athi);
    cudaGetSymbolAddress((void**)&atlo, g_atlo);
    cudaGetSymbolAddress((void**)&zhi,  g_zhi);
    cudaGetSymbolAddress((void**)&zlo,  g_zlo);

    static cudaStream_t s1;
    static cudaEvent_t evFork, evJoin;
    static int inited = 0;
    if (!inited) {
        cudaStreamCreateWithFlags(&s1, cudaStreamNonBlocking);
        cudaEventCreateWithFlags(&evFork, cudaEventDisableTiming);
        cudaEventCreateWithFlags(&evJoin, cudaEventDisableTiming);
        cudaFuncSetAttribute(tcmma, cudaFuncAttributeMaxDynamicSharedMemorySize, MM_SMEM);
        cudaFuncSetAttribute(tcmma_ln, cudaFuncAttributeMaxDynamicSharedMemorySize, FL_SMEM);
        cudaFuncSetAttribute(attn_mma_kernel, cudaFuncAttributeMaxDynamicSharedMemorySize, AT_SMEM);
        inited = 1;
    }

    // fork: branch B (splits + QKV GEMM) on s1, branch A (detlut/maskfuse) on 0
    cudaEventRecord(evFork, 0);
    cudaStreamWaitEvent(s1, evFork, 0);

    prep_split<<<2688, 256, 0, s1>>>(x, (const float*)d_in[3], (const float*)d_in[4],
                                     (const float*)d_in[5], (const float*)d_in[10],
                                     (const float*)d_in[12]);
    tcmma<<<dim3(32, 4, 3), 256, MM_SMEM, s1>>>(xhi, xlo, 0, qraw);

    detlut_kernel<<<264, 256>>>((const unsigned*)mask, pw1, pb1, pw2, pb2);
    maskfuse_kernel<<<4096, 256>>>(rel, mask);

    cudaEventRecord(evJoin, s1);
    cudaStreamWaitEvent(0, evJoin, 0);

    attn_mma_kernel<<<dim3(8, 32), 256, AT_SMEM>>>();

    // fused tail: GEMM + residual LN in one kernel each
    tcmma_ln<<<128, 256, FL_SMEM>>>(athi, atlo, 3, bo, x, g1, be1, zz, zhi, zlo, 0);
    tcmma_ln<<<128, 256, FL_SMEM>>>(zhi, zlo, 4, bfv, zz, g2, be2, (float*)d_out,
                                    nullptr, nullptr, 1);
}

// round 17
// speedup vs baseline: 1.1551x; 1.0831x over previous
#include <cuda_runtime.h>
#include <cuda_bf16.h>

#define BB  4
#define TT  1024
#define DD  256
#define HH  8
#define CC  16
#define BT  (BB*TT)

typedef unsigned long long ull;

__device__ __forceinline__ unsigned smem_u32(const void* p) {
    unsigned a;
    asm("{ .reg .u64 t; cvta.to.shared.u64 t, %1; cvt.u32.u64 %0, t; }" : "=r"(a) : "l"(p));
    return a;
}
__device__ __forceinline__ void ldsm4(unsigned* r, unsigned addr) {
    asm volatile("ldmatrix.sync.aligned.m8n8.x4.shared.b16 {%0,%1,%2,%3}, [%4];"
                 : "=r"(r[0]), "=r"(r[1]), "=r"(r[2]), "=r"(r[3]) : "r"(addr));
}
__device__ __forceinline__ void mma16816(float* c, const unsigned* a, const unsigned* b) {
    asm volatile("mma.sync.aligned.m16n8k16.row.col.f32.bf16.bf16.f32 "
                 "{%0,%1,%2,%3}, {%4,%5,%6,%7}, {%8,%9}, {%0,%1,%2,%3};"
                 : "+f"(c[0]), "+f"(c[1]), "+f"(c[2]), "+f"(c[3])
                 : "r"(a[0]), "r"(a[1]), "r"(a[2]), "r"(a[3]), "r"(b[0]), "r"(b[1]));
}
__device__ __forceinline__ unsigned cvt2bf(float hi, float lo) {
    unsigned r;
    asm("cvt.rn.bf16x2.f32 %0, %1, %2;" : "=r"(r) : "f"(hi), "f"(lo));
    return r;
}
__device__ __forceinline__ void cpa16(unsigned dst, const void* src) {
    asm volatile("cp.async.cg.shared.global [%0], [%1], 16;" :: "r"(dst), "l"(src));
}
#define CPA_COMMIT() asm volatile("cp.async.commit_group;" ::: "memory")
#define CPA_WAIT0()  asm volatile("cp.async.wait_group 0;" ::: "memory")

// ---------------- scratch ----------------
__device__ float g_zz[BT*DD];
__device__ unsigned char g_mdx[BB*TT*TT];   // u8: 255=masked, else idx 0..254
__device__ float g_lutv[HH*256];
__device__ int   g_mask_flags = 0;          // idempotent: same bits OR'd every call
__device__ __nv_bfloat16 g_xhi[BT*DD],  g_xlo[BT*DD];
__device__ __nv_bfloat16 g_athi[BT*DD], g_atlo[BT*DD];
__device__ __nv_bfloat16 g_zhi[BT*DD],  g_zlo[BT*DD];
__device__ __nv_bfloat16 g_whi[5*DD*DD], g_wlo[5*DD*DD];
__device__ __nv_bfloat16 g_vthi[32*HH*BB*TT], g_vtlo[32*HH*BB*TT]; // [bh][32][1024]
__device__ __nv_bfloat16 g_qh2[HH*BB*TT*32], g_ql2[HH*BB*TT*32];   // [bh][t][32]
__device__ __nv_bfloat16 g_kh2[HH*BB*TT*32], g_kl2[HH*BB*TT*32];
__device__ float g_qraw[BT*DD];  // scratch for QKV z-output routing

// ---------------------------------------------------------------------------
// Merged detect + LUT build.
// ---------------------------------------------------------------------------
__global__ void detlut_kernel(const unsigned* __restrict__ w,
                              const float* __restrict__ pw1, const float* __restrict__ pb1,
                              const float* __restrict__ pw2, const float* __restrict__ pb2)
{
    if (blockIdx.x < 256) {
        int i = blockIdx.x * 256 + threadIdx.x;
        unsigned x = w[i];
        int f = 0;
        if (x == 0x3F800000u)               f = 2;
        else if ((x & 0xFFFFu) == 0x3F80u)  f = 4;
        else if (x > 1u)                    f = 1;
        if (f) atomicOr(&g_mask_flags, f);
        return;
    }
    __shared__ float sc[34];
    int h = blockIdx.x - 256;
    int t = threadIdx.x;
    if (t < 16) {
        float w1 = pw1[h*CC + t], b1 = pb1[h*CC + t], w2 = pw2[h*CC + t];
        float beta, delta, k0add, k1add;
        if (w1 != 0.0f) {
            beta  = 0.495f * w2 * fabsf(w1);
            delta = -b1 / w1;
            k0add = 0.505f * w2 * b1;
            k1add = 0.505f * w2 * w1;
        } else {
            beta = 0.0f; delta = 0.0f;
            k0add = w2 * (0.505f * b1 + 0.495f * fabsf(b1));
            k1add = 0.0f;
        }
        #pragma unroll
        for (int off = 1; off < 16; off <<= 1) {
            k0add += __shfl_xor_sync(0x0000FFFFu, k0add, off);
            k1add += __shfl_xor_sync(0x0000FFFFu, k1add, off);
        }
        sc[2 + t]  = beta;
        sc[18 + t] = delta;
        if (t == 0) {
            sc[0] = pb2[h] + k0add;
            sc[1] = k1add;
        }
    }
    __syncthreads();
    if (t == 255) { g_lutv[h*256 + 255] = 0.0f; return; }
    float m = (t + 0.5f) * (1.0f / 255.0f);
    float v = sc[0] + sc[1] * m;
    #pragma unroll
    for (int c = 0; c < 16; c++)
        v += sc[2 + c] * fabsf(m - sc[18 + c]);
    g_lutv[h*256 + t] = -v;
}

__global__ __launch_bounds__(256) void maskfuse_kernel(const float* __restrict__ rd,
                                                       const void* __restrict__ maskp)
{
    int i = blockIdx.x * 256 + threadIdx.x;
    size_t base = (size_t)i * 4;
    int mf = g_mask_flags;
    int mode = (mf & 4) ? 3 : (mf & 2) ? 2 : (mf & 1) ? 1 : 0;
    float4 d4 = *(const float4*)&rd[base];
    int m0, m1, m2, m3;
    if (mode == 0) {
        int4 m = *(const int4*)((const int*)maskp + base);
        m0 = m.x != 0; m1 = m.y != 0; m2 = m.z != 0; m3 = m.w != 0;
    } else if (mode == 1) {
        uchar4 m = *(const uchar4*)((const unsigned char*)maskp + base);
        m0 = m.x != 0; m1 = m.y != 0; m2 = m.z != 0; m3 = m.w != 0;
    } else if (mode == 2) {
        float4 m = *(const float4*)((const float*)maskp + base);
        m0 = m.x != 0.0f; m1 = m.y != 0.0f; m2 = m.z != 0.0f; m3 = m.w != 0.0f;
    } else {
        ushort4 m = *(const ushort4*)((const unsigned short*)maskp + base);
        m0 = m.x != 0; m1 = m.y != 0; m2 = m.z != 0; m3 = m.w != 0;
    }
    int i0 = min(max(__float2int_rd(d4.x * 255.0f), 0), 254);
    int i1 = min(max(__float2int_rd(d4.y * 255.0f), 0), 254);
    int i2 = min(max(__float2int_rd(d4.z * 255.0f), 0), 254);
    int i3 = min(max(__float2int_rd(d4.w * 255.0f), 0), 254);
    uchar4 o;
    o.x = (unsigned char)(m0 ? 255 : i0);
    o.y = (unsigned char)(m1 ? 255 : i1);
    o.z = (unsigned char)(m2 ? 255 : i2);
    o.w = (unsigned char)(m3 ? 255 : i3);
    *(uchar4*)&g_mdx[base] = o;
}

__global__ __launch_bounds__(256) void prep_split(const float* __restrict__ x,
                                                  const float* __restrict__ w0,
                                                  const float* __restrict__ w1,
                                                  const float* __restrict__ w2,
                                                  const float* __restrict__ w3,
                                                  const float* __restrict__ w4)
{
    const float* src;
    __nv_bfloat16 *hi, *lo;
    size_t e;
    if (blockIdx.x < 640) {
        int i = blockIdx.x * 256 + threadIdx.x;
        e = (size_t)i * 2;
        int w = (int)(e >> 16);
        size_t off = e & 65535;
        src = ((w == 0) ? w0 : (w == 1) ? w1 : (w == 2) ? w2 : (w == 3) ? w3 : w4) + off - e;
        hi = g_whi; lo = g_wlo;
    } else {
        int i = (blockIdx.x - 640) * 256 + threadIdx.x;
        e = (size_t)i * 2;
        src = x;
        hi = g_xhi; lo = g_xlo;
    }
    float2 v = *(const float2*)&src[e];
    __nv_bfloat16 hx = __float2bfloat16(v.x), hy = __float2bfloat16(v.y);
    __nv_bfloat162 h2; h2.x = hx; h2.y = hy;
    __nv_bfloat162 l2;
    l2.x = __float2bfloat16(v.x - __bfloat162float(hx));
    l2.y = __float2bfloat16(v.y - __bfloat162float(hy));
    *(__nv_bfloat162*)&hi[e] = h2;
    *(__nv_bfloat162*)&lo[e] = l2;
}

// ---------------------------------------------------------------------------
// HMMA GEMM (bf16x3), cp.async double-buffered — QKV flavor.
// z<2 -> fused L2-norm + split to q/k layout; z==2 -> fused transpose + split V^T.
// ---------------------------------------------------------------------------
#define MM_AHI 0
#define MM_ALO 18432
#define MM_WHI 36864
#define MM_WLO 46080
#define MM_BUF 55296
#define MM_SMEM (2*MM_BUF)

__global__ __launch_bounds__(256) void tcmma(const __nv_bfloat16* __restrict__ Ahi,
                                             const __nv_bfloat16* __restrict__ Alo,
                                             int widx0,
                                             float* __restrict__ C0)
{
    extern __shared__ char sm[];
    unsigned smb = smem_u32(sm);
    int tid = threadIdx.x;
    int lane = tid & 31;
    int wid = tid >> 5;
    int wm = wid & 3;
    int wn = wid >> 2;
    int m0 = blockIdx.x * 128, n0 = blockIdx.y * 64;
    int z = blockIdx.z;
    const __nv_bfloat16* Whi = g_whi + (size_t)(widx0 + z) * (DD*DD);
    const __nv_bfloat16* Wlo = g_wlo + (size_t)(widx0 + z) * (DD*DD);

    auto stage = [&](int kc, unsigned bo) {
        #pragma unroll
        for (int it = 0; it < 4; it++) {
            int v = tid + it * 256;
            int row = v >> 3, cg = (v & 7) * 8;
            size_t gofs = (size_t)(m0 + row) * 256 + kc * 64 + cg;
            cpa16(smb + bo + MM_AHI + row*144 + cg*2, &Ahi[gofs]);
            cpa16(smb + bo + MM_ALO + row*144 + cg*2, &Alo[gofs]);
        }
        #pragma unroll
        for (int it = 0; it < 2; it++) {
            int v = tid + it * 256;
            int row = v >> 3, cg = (v & 7) * 8;
            size_t gofs = (size_t)(n0 + row) * 256 + kc * 64 + cg;
            cpa16(smb + bo + MM_WHI + row*144 + cg*2, &Whi[gofs]);
            cpa16(smb + bo + MM_WLO + row*144 + cg*2, &Wlo[gofs]);
        }
    };

    float acc[2][4][4];
    #pragma unroll
    for (int a = 0; a < 2; a++)
        #pragma unroll
        for (int b = 0; b < 4; b++)
            #pragma unroll
            for (int c = 0; c < 4; c++) acc[a][b][c] = 0.0f;

    stage(0, 0);
    CPA_COMMIT();

    for (int kc = 0; kc < 4; kc++) {
        CPA_WAIT0();
        __syncthreads();
        unsigned bo = (unsigned)(kc & 1) * MM_BUF;
        if (kc < 3) { stage(kc + 1, bo ^ MM_BUF); CPA_COMMIT(); }

        #pragma unroll
        for (int ks = 0; ks < 4; ks++) {
            int kb = ks * 16;
            unsigned ah[2][4], al[2][4], bh[2][4], bl[2][4];
            #pragma unroll
            for (int mi = 0; mi < 2; mi++) {
                int row = wm*32 + mi*16 + (lane & 15);
                unsigned ad = smb + bo + MM_AHI + row*144 + (kb + ((lane >> 4) << 3)) * 2;
                ldsm4(ah[mi], ad);
                ldsm4(al[mi], ad + (MM_ALO - MM_AHI));
            }
            #pragma unroll
            for (int gi = 0; gi < 2; gi++) {
                int nrow = wn*32 + gi*16 + (lane & 7) + ((lane >> 4) & 1) * 8;
                unsigned bd = smb + bo + MM_WHI + nrow*144 + (kb + (((lane >> 3) & 1) << 3)) * 2;
                ldsm4(bh[gi], bd);
                ldsm4(bl[gi], bd + (MM_WLO - MM_WHI));
            }
            #pragma unroll
            for (int mi = 0; mi < 2; mi++) {
                #pragma unroll
                for (int ni = 0; ni < 4; ni++) {
                    int gi = ni >> 1, hf = (ni & 1) * 2;
                    mma16816(acc[mi][ni], ah[mi], &bh[gi][hf]);
                    mma16816(acc[mi][ni], ah[mi], &bl[gi][hf]);
                    mma16816(acc[mi][ni], al[mi], &bh[gi][hf]);
                }
            }
        }
    }

    if (z != 2) {
        __nv_bfloat16* dsthi = (z == 0) ? g_qh2 : g_kh2;
        __nv_bfloat16* dstlo = (z == 0) ? g_ql2 : g_kl2;
        int head = blockIdx.y * 2 + wn;
        #pragma unroll
        for (int mi = 0; mi < 2; mi++) {
            #pragma unroll
            for (int rr = 0; rr < 2; rr++) {
                float v[8];
                #pragma unroll
                for (int ni = 0; ni < 4; ni++) {
                    v[ni*2]   = acc[mi][ni][rr*2];
                    v[ni*2+1] = acc[mi][ni][rr*2+1];
                }
                float ss = 0.0f;
                #pragma unroll
                for (int j = 0; j < 8; j++) ss = fmaf(v[j], v[j], ss);
                ss += __shfl_xor_sync(0xffffffffu, ss, 1);
                ss += __shfl_xor_sync(0xffffffffu, ss, 2);
                float inv = 1.0f / fmaxf(sqrtf(ss), 1e-12f);
                int row = m0 + wm*32 + mi*16 + rr*8 + (lane >> 2);
                int b = row >> 10, t = row & 1023;
                size_t base = (((size_t)(b*8 + head)) * 1024 + t) * 32 + (lane & 3) * 2;
                #pragma unroll
                for (int ni = 0; ni < 4; ni++) {
                    float v0 = v[ni*2] * inv, v1 = v[ni*2+1] * inv;
                    unsigned hh = cvt2bf(v1, v0);
                    float f0 = __uint_as_float(hh << 16), f1 = __uint_as_float(hh & 0xFFFF0000u);
                    *(unsigned*)&dsthi[base + ni*8] = hh;
                    *(unsigned*)&dstlo[base + ni*8] = cvt2bf(v1 - f1, v0 - f0);
                }
            }
        }
        return;
    }
    // z == 2: V. Transpose via smem, split hi/lo, write [bh][c][t].
    __syncthreads();
    float* sT = (float*)sm;          // [64 cols][132]
    int rbase_l = wm*32 + (lane >> 2);
    int cbase_l = wn*32 + (lane & 3) * 2;
    #pragma unroll
    for (int mi = 0; mi < 2; mi++) {
        #pragma unroll
        for (int ni = 0; ni < 4; ni++) {
            int col = cbase_l + ni*8;
            int row = rbase_l + mi*16;
            sT[(col+0)*132 + row]     = acc[mi][ni][0];
            sT[(col+1)*132 + row]     = acc[mi][ni][1];
            sT[(col+0)*132 + row + 8] = acc[mi][ni][2];
            sT[(col+1)*132 + row + 8] = acc[mi][ni][3];
        }
    }
    __syncthreads();
    int colg = tid >> 2;
    int tr   = (tid & 3) * 32;
    int head = blockIdx.y * 2 + (colg >> 5);
    int c    = colg & 31;
    int b    = m0 >> 10;
    size_t o = (((size_t)(b*8 + head)) * 32 + c) * 1024 + (m0 & 1023) + tr;
    const float* srcp = &sT[colg*132 + tr];
    unsigned hp[16], lp[16];
    #pragma unroll
    for (int j = 0; j < 16; j++) {
        float v0 = srcp[2*j], v1 = srcp[2*j+1];
        unsigned hh = cvt2bf(v1, v0);
        float f0 = __uint_as_float(hh << 16), f1 = __uint_as_float(hh & 0xFFFF0000u);
        hp[j] = hh;
        lp[j] = cvt2bf(v1 - f1, v0 - f0);
    }
    #pragma unroll
    for (int j = 0; j < 4; j++) {
        *(uint4*)&g_vthi[o + j*8] = make_uint4(hp[j*4], hp[j*4+1], hp[j*4+2], hp[j*4+3]);
        *(uint4*)&g_vtlo[o + j*8] = make_uint4(lp[j*4], lp[j*4+1], lp[j*4+2], lp[j*4+3]);
    }
}

// ---------------------------------------------------------------------------
// Full-row GEMM + fused residual LayerNorm (bf16x3). (unchanged from R16)
// ---------------------------------------------------------------------------
#define FL_AHI 0
#define FL_ALO 4608
#define FL_WHI 9216
#define FL_WLO 46080
#define FL_BUF 82944
#define FL_SMEM (2*FL_BUF)

__global__ __launch_bounds__(256) void tcmma_ln(const __nv_bfloat16* __restrict__ Ahi,
                                                const __nv_bfloat16* __restrict__ Alo,
                                                int widx,
                                                const float* __restrict__ bias,
                                                const float* __restrict__ resid,
                                                const float* __restrict__ gam,
                                                const float* __restrict__ bet,
                                                float* __restrict__ outf,
                                                __nv_bfloat16* __restrict__ outhi,
                                                __nv_bfloat16* __restrict__ outlo,
                                                int act)
{
    extern __shared__ char sm[];
    unsigned smb = smem_u32(sm);
    int tid = threadIdx.x;
    int lane = tid & 31;
    int wid = tid >> 5;
    int wm = wid >> 2;
    int wn = wid & 3;
    int m0 = blockIdx.x * 32;
    const __nv_bfloat16* Whi = g_whi + (size_t)widx * (DD*DD);
    const __nv_bfloat16* Wlo = g_wlo + (size_t)widx * (DD*DD);

    auto stage = [&](int kc, unsigned bo) {
        {
            int row = tid >> 3, cg = (tid & 7) * 8;
            size_t gofs = (size_t)(m0 + row) * 256 + kc * 64 + cg;
            cpa16(smb + bo + FL_AHI + row*144 + cg*2, &Ahi[gofs]);
            cpa16(smb + bo + FL_ALO + row*144 + cg*2, &Alo[gofs]);
        }
        #pragma unroll
        for (int it = 0; it < 8; it++) {
            int v = tid + it * 256;
            int row = v >> 3, cg = (v & 7) * 8;
            size_t gofs = (size_t)row * 256 + kc * 64 + cg;
            cpa16(smb + bo + FL_WHI + row*144 + cg*2, &Whi[gofs]);
            cpa16(smb + bo + FL_WLO + row*144 + cg*2, &Wlo[gofs]);
        }
    };

    float acc[8][4];
    #pragma unroll
    for (int i = 0; i < 8; i++)
        #pragma unroll
        for (int j = 0; j < 4; j++) acc[i][j] = 0.0f;

    stage(0, 0);
    CPA_COMMIT();

    for (int kc = 0; kc < 4; kc++) {
        CPA_WAIT0();
        __syncthreads();
        unsigned bo = (unsigned)(kc & 1) * FL_BUF;
        if (kc < 3) { stage(kc + 1, bo ^ FL_BUF); CPA_COMMIT(); }

        #pragma unroll
        for (int ks = 0; ks < 4; ks++) {
            int kb = ks * 16;
            unsigned ah[4], al[4], bh[4][4], bl[4][4];
            {
                int row = wm*16 + (lane & 15);
                unsigned ad = smb + bo + FL_AHI + row*144 + (kb + ((lane >> 4) << 3)) * 2;
                ldsm4(ah, ad);
                ldsm4(al, ad + (FL_ALO - FL_AHI));
            }
            #pragma unroll
            for (int gi = 0; gi < 4; gi++) {
                int nrow = wn*64 + gi*16 + (lane & 7) + ((lane >> 4) & 1) * 8;
                unsigned bd = smb + bo + FL_WHI + nrow*144 + (kb + (((lane >> 3) & 1) << 3)) * 2;
                ldsm4(bh[gi], bd);
                ldsm4(bl[gi], bd + (FL_WLO - FL_WHI));
            }
            #pragma unroll
            for (int ni = 0; ni < 8; ni++) {
                int gi = ni >> 1, hf = (ni & 1) * 2;
                mma16816(acc[ni], ah, &bh[gi][hf]);
                mma16816(acc[ni], ah, &bl[gi][hf]);
                mma16816(acc[ni], al, &bh[gi][hf]);
            }
        }
    }

    __syncthreads();
    float* sO = (float*)sm;    // [32][260]
    int rb = wm*16 + (lane >> 2);
    int cb = wn*64 + (lane & 3) * 2;
    #pragma unroll
    for (int ni = 0; ni < 8; ni++) {
        int col = cb + ni*8;
        float b0 = bias[col], b1 = bias[col + 1];
        float v0 = acc[ni][0] + b0;
        float v1 = acc[ni][1] + b1;
        float v2 = acc[ni][2] + b0;
        float v3 = acc[ni][3] + b1;
        if (act) {
            v0 = (v0 >= 0.0f) ? v0 : 0.01f * v0;
            v1 = (v1 >= 0.0f) ? v1 : 0.01f * v1;
            v2 = (v2 >= 0.0f) ? v2 : 0.01f * v2;
            v3 = (v3 >= 0.0f) ? v3 : 0.01f * v3;
        }
        sO[rb*260 + col]       = v0;
        sO[rb*260 + col + 1]   = v1;
        sO[(rb+8)*260 + col]     = v2;
        sO[(rb+8)*260 + col + 1] = v3;
    }
    __syncthreads();

    #pragma unroll
    for (int rr = 0; rr < 4; rr++) {
        int r = wid*4 + rr;
        int grow = m0 + r;
        const float* rp = resid + (size_t)grow * 256;
        float v[8]; float s = 0.0f;
        #pragma unroll
        for (int u = 0; u < 8; u++) {
            int col = lane + 32*u;
            v[u] = rp[col] + sO[r*260 + col];
            s += v[u];
        }
        #pragma unroll
        for (int off = 16; off; off >>= 1) s += __shfl_xor_sync(0xffffffffu, s, off);
        float mu = s * (1.0f / 256.0f);
        float vs = 0.0f;
        #pragma unroll
        for (int u = 0; u < 8; u++) { float d = v[u] - mu; vs = fmaf(d, d, vs); }
        #pragma unroll
        for (int off = 16; off; off >>= 1) vs += __shfl_xor_sync(0xffffffffu, vs, off);
        float rstd = rsqrtf(vs * (1.0f / 256.0f) + 1e-5f);
        #pragma unroll
        for (int u = 0; u < 8; u++) {
            int col = lane + 32*u;
            float o = (v[u] - mu) * rstd * gam[col] + bet[col];
            outf[(size_t)grow * 256 + col] = o;
            if (outhi) {
                __nv_bfloat16 hh = __float2bfloat16(o);
                outhi[(size_t)grow * 256 + col] = hh;
                outlo[(size_t)grow * 256 + col] = __float2bfloat16(o - __bfloat162float(hh));
            }
        }
    }
}

// ---------------------------------------------------------------------------
// HMMA attention — now __launch_bounds__(256, 2) to force 2 CTAs/SM.
// ---------------------------------------------------------------------------
#define AT_QHI 0
#define AT_QLO 10240
#define AT_KV  20480
#define AT_KVBUF 19456
#define AT_LUT 59392
#define AT_SMEM 60416

__global__ __launch_bounds__(256, 2) void attn_mma_kernel()
{
    extern __shared__ __align__(16) char SM_[];
    unsigned smb = smem_u32(SM_);
    float* sLUT = (float*)(SM_ + AT_LUT);

    int tid = threadIdx.x;
    int lane = tid & 31;
    int wid = tid >> 5;
    int wq = wid & 3;
    int ws = wid >> 2;
    int bh = blockIdx.y, b = bh >> 3, h = bh & 7;
    int t0 = blockIdx.x << 7;

    auto stageKV = [&](int s0, unsigned gb) {
        int row = tid >> 2, cg = (tid & 3) * 8;
        size_t gofs = (((size_t)bh * TT) + s0 + row) * 32 + cg;
        cpa16(smb + gb + 0     + row*80 + cg*2, &g_kh2[gofs]);
        cpa16(smb + gb + 5120  + row*80 + cg*2, &g_kl2[gofs]);
        int c = tid >> 3, sg = (tid & 7) * 8;
        size_t vofs = ((size_t)bh * 32 + c) * 1024 + s0 + sg;
        cpa16(smb + gb + 10240 + c*144 + sg*2, &g_vthi[vofs]);
        cpa16(smb + gb + 14848 + c*144 + sg*2, &g_vtlo[vofs]);
    };

    sLUT[tid] = g_lutv[h*256 + tid];
    #pragma unroll
    for (int r2 = 0; r2 < 2; r2++) {
        int row = (tid >> 2) + r2*64, cg = (tid & 3) * 8;
        size_t gofs = (((size_t)bh * TT) + t0 + row) * 32 + cg;
        *(uint4*)(SM_ + AT_QHI + row*80 + cg*2) = *(const uint4*)&g_qh2[gofs];
        *(uint4*)(SM_ + AT_QLO + row*80 + cg*2) = *(const uint4*)&g_ql2[gofs];
    }
    stageKV(0, AT_KV);
    CPA_COMMIT();

    float oacc[2][4][4];
    #pragma unroll
    for (int mi = 0; mi < 2; mi++)
        #pragma unroll
        for (int i = 0; i < 4; i++)
            #pragma unroll
            for (int j = 0; j < 4; j++) oacc[mi][i][j] = 0.0f;
    float zs[2][2] = {{0.f,0.f},{0.f,0.f}};

    int qrow_f = (lane >> 2);
    int ccol_f = (lane & 3) * 2;

    #pragma unroll 1
    for (int st = 0; st < 16; st++) {
        int s0 = st << 6;
        CPA_WAIT0();
        __syncthreads();
        unsigned gb = AT_KV + (unsigned)(st & 1) * AT_KVBUF;
        if (st < 15) { stageKV(s0 + 64, gb == AT_KV ? AT_KV + AT_KVBUF : AT_KV); CPA_COMMIT(); }

        uchar2 md[2][4][2];
        {
            size_t mb = (size_t)b * TT * TT;
            int gcb = s0 + ws*32 + ccol_f;
            #pragma unroll
            for (int mi = 0; mi < 2; mi++) {
                int gr = t0 + wq*32 + mi*16 + qrow_f;
                #pragma unroll
                for (int ni = 0; ni < 4; ni++) {
                    md[mi][ni][0] = *(const uchar2*)&g_mdx[mb + (size_t)gr * TT + gcb + ni*8];
                    md[mi][ni][1] = *(const uchar2*)&g_mdx[mb + (size_t)(gr+8) * TT + gcb + ni*8];
                }
            }
        }

        float sacc[2][4][4];
        #pragma unroll
        for (int mi = 0; mi < 2; mi++)
            #pragma unroll
            for (int i = 0; i < 4; i++)
                #pragma unroll
                for (int j = 0; j < 4; j++) sacc[mi][i][j] = 0.0f;

        #pragma unroll
        for (int ks = 0; ks < 2; ks++) {
            int kb = ks * 16;
            unsigned ah[2][4], al[2][4], bhf[2][4], blf[2][4];
            #pragma unroll
            for (int mi = 0; mi < 2; mi++) {
                int row = wq*32 + mi*16 + (lane & 15);
                unsigned ad = smb + AT_QHI + row*80 + (kb + ((lane >> 4) << 3)) * 2;
                ldsm4(ah[mi], ad);
                ldsm4(al[mi], ad + (AT_QLO - AT_QHI));
            }
            #pragma unroll
            for (int gi = 0; gi < 2; gi++) {
                int nrow = ws*32 + gi*16 + (lane & 7) + ((lane >> 4) & 1) * 8;
                unsigned bd = smb + gb + 0 + nrow*80 + (kb + (((lane >> 3) & 1) << 3)) * 2;
                ldsm4(bhf[gi], bd);
                ldsm4(blf[gi], bd + 5120);
            }
            #pragma unroll
            for (int mi = 0; mi < 2; mi++) {
                #pragma unroll
                for (int ni = 0; ni < 4; ni++) {
                    int gi = ni >> 1, hf = (ni & 1) * 2;
                    mma16816(sacc[mi][ni], ah[mi], &bhf[gi][hf]);
                    mma16816(sacc[mi][ni], ah[mi], &blf[gi][hf]);
                    mma16816(sacc[mi][ni], al[mi], &bhf[gi][hf]);
                }
            }
        }

        unsigned phi[2][8], plo[2][8];
        #pragma unroll
        for (int mi = 0; mi < 2; mi++) {
            #pragma unroll
            for (int ni = 0; ni < 4; ni++) {
                uchar2 m0 = md[mi][ni][0], m1 = md[mi][ni][1];
                float z0 = (m0.x == 255) ? 0.0f : __expf(sacc[mi][ni][0] + sLUT[m0.x]);
                float z1 = (m0.y == 255) ? 0.0f : __expf(sacc[mi][ni][1] + sLUT[m0.y]);
                float z2 = (m1.x == 255) ? 0.0f : __expf(sacc[mi][ni][2] + sLUT[m1.x]);
                float z3 = (m1.y == 255) ? 0.0f : __expf(sacc[mi][ni][3] + sLUT[m1.y]);
                zs[mi][0] += z0 + z1;
                zs[mi][1] += z2 + z3;
                unsigned p01 = cvt2bf(z1, z0);
                unsigned p23 = cvt2bf(z3, z2);
                phi[mi][ni*2]   = p01;
                phi[mi][ni*2+1] = p23;
                float f0 = __uint_as_float(p01 << 16), f1 = __uint_as_float(p01 & 0xFFFF0000u);
                float f2 = __uint_as_float(p23 << 16), f3 = __uint_as_float(p23 & 0xFFFF0000u);
                plo[mi][ni*2]   = cvt2bf(z1 - f1, z0 - f0);
                plo[mi][ni*2+1] = cvt2bf(z3 - f3, z2 - f2);
            }
        }

        #pragma unroll
        for (int kf = 0; kf < 2; kf++) {
            unsigned vbh[2][4], vbl[2][4];
            #pragma unroll
            for (int gi = 0; gi < 2; gi++) {
                int nrow = gi*16 + (lane & 7) + ((lane >> 4) & 1) * 8;
                int col = ws*32 + kf*16 + (((lane >> 3) & 1) << 3);
                unsigned bd = smb + gb + 10240 + nrow*144 + col*2;
                ldsm4(vbh[gi], bd);
                ldsm4(vbl[gi], bd + 4608);
            }
            #pragma unroll
            for (int mi = 0; mi < 2; mi++) {
                #pragma unroll
                for (int ni = 0; ni < 4; ni++) {
                    int gi = ni >> 1, hf = (ni & 1) * 2;
                    mma16816(oacc[mi][ni], &phi[mi][4*kf], &vbh[gi][hf]);
                    mma16816(oacc[mi][ni], &plo[mi][4*kf], &vbh[gi][hf]);
                    mma16816(oacc[mi][ni], &phi[mi][4*kf], &vbl[gi][hf]);
                }
            }
        }
    }

    #pragma unroll
    for (int mi = 0; mi < 2; mi++) {
        zs[mi][0] += __shfl_xor_sync(0xffffffffu, zs[mi][0], 1);
        zs[mi][0] += __shfl_xor_sync(0xffffffffu, zs[mi][0], 2);
        zs[mi][1] += __shfl_xor_sync(0xffffffffu, zs[mi][1], 1);
        zs[mi][1] += __shfl_xor_sync(0xffffffffu, zs[mi][1], 2);
    }
    __syncthreads();

    float* sO  = (float*)(SM_ + 0);        // [128][34]
    float* sRS = (float*)(SM_ + 18432);    // [128]
    if (ws == 1) {
        #pragma unroll
        for (int mi = 0; mi < 2; mi++) {
            int r = wq*32 + mi*16 + qrow_f;
            if ((lane & 3) == 0) {
                sRS[r]     = zs[mi][0];
                sRS[r + 8] = zs[mi][1];
            }
            #pragma unroll
            for (int ni = 0; ni < 4; ni++) {
                int c = ni*8 + ccol_f;
                *(float2*)&sO[r*34 + c]     = make_float2(oacc[mi][ni][0], oacc[mi][ni][1]);
                *(float2*)&sO[(r+8)*34 + c] = make_float2(oacc[mi][ni][2], oacc[mi][ni][3]);
            }
        }
    }
    __syncthreads();
    if (ws == 0) {
        #pragma unroll
        for (int mi = 0; mi < 2; mi++) {
            int r = wq*32 + mi*16 + qrow_f;
            float inv0 = 1.0f / (zs[mi][0] + sRS[r]     + 1e-5f);
            float inv8 = 1.0f / (zs[mi][1] + sRS[r + 8] + 1e-5f);
            size_t o0 = ((size_t)b * TT + t0 + r)     * DD + h * 32;
            size_t o8 = ((size_t)b * TT + t0 + r + 8) * DD + h * 32;
            #pragma unroll
            for (int ni = 0; ni < 4; ni++) {
                int c = ni*8 + ccol_f;
                float2 p0 = *(const float2*)&sO[r*34 + c];
                float2 p8 = *(const float2*)&sO[(r+8)*34 + c];
                float v0 = (oacc[mi][ni][0] + p0.x) * inv0;
                float v1 = (oacc[mi][ni][1] + p0.y) * inv0;
                float v2 = (oacc[mi][ni][2] + p8.x) * inv8;
                float v3 = (oacc[mi][ni][3] + p8.y) * inv8;
                unsigned h0 = cvt2bf(v1, v0);
                unsigned h8 = cvt2bf(v3, v2);
                float f0 = __uint_as_float(h0 << 16), f1 = __uint_as_float(h0 & 0xFFFF0000u);
                float f2 = __uint_as_float(h8 << 16), f3 = __uint_as_float(h8 & 0xFFFF0000u);
                *(unsigned*)&g_athi[o0 + c] = h0;
                *(unsigned*)&g_atlo[o0 + c] = cvt2bf(v1 - f1, v0 - f0);
                *(unsigned*)&g_athi[o8 + c] = h8;
                *(unsigned*)&g_atlo[o8 + c] = cvt2bf(v3 - f3, v2 - f2);
            }
        }
    }
}

extern "C" void kernel_launch(void* const* d_in, const int* in_sizes, int n_in,
                              void* d_out, int out_size)
{
    const float* x    = (const float*)d_in[0];
    const void*  mask = d_in[1];
    const float* rel  = (const float*)d_in[2];
    const float* pw1  = (const float*)d_in[6];
    const float* pb1  = (const float*)d_in[7];
    const float* pw2  = (const float*)d_in[8];
    const float* pb2  = (const float*)d_in[9];
    const float* bo   = (const float*)d_in[11];
    const float* bfv  = (const float*)d_in[13];
    const float* g1   = (const float*)d_in[14];
    const float* be1  = (const float*)d_in[15];
    const float* g2   = (const float*)d_in[16];
    const float* be2  = (const float*)d_in[17];

    float *zz, *qraw;
    __nv_bfloat16 *xhi, *xlo, *athi, *atlo, *zhi, *zlo;
    cudaGetSymbolAddress((void**)&zz,   g_zz);
    cudaGetSymbolAddress((void**)&qraw, g_qraw);
    cudaGetSymbolAddress((void**)&xhi,  g_xhi);
    cudaGetSymbolAddress((void**)&xlo,  g_xlo);
    cudaGetSymbolAddress((void**)&athi, g_athi);
    cudaGetSymbolAddress((void**)&atlo, g_atlo);
    cudaGetSymbolAddress((void**)&zhi,  g_zhi);
    cudaGetSymbolAddress((void**)&zlo,  g_zlo);

    static cudaStream_t s1;
    static cudaEvent_t evFork, evJoin;
    static int inited = 0;
    if (!inited) {
        cudaStreamCreateWithFlags(&s1, cudaStreamNonBlocking);
        cudaEventCreateWithFlags(&evFork, cudaEventDisableTiming);
        cudaEventCreateWithFlags(&evJoin, cudaEventDisableTiming);
        cudaFuncSetAttribute(tcmma, cudaFuncAttributeMaxDynamicSharedMemorySize, MM_SMEM);
        cudaFuncSetAttribute(tcmma_ln, cudaFuncAttributeMaxDynamicSharedMemorySize, FL_SMEM);
        cudaFuncSetAttribute(attn_mma_kernel, cudaFuncAttributeMaxDynamicSharedMemorySize, AT_SMEM);
        inited = 1;
    }

    // fork: branch B (splits + QKV GEMM) on s1, branch A (detlut/maskfuse) on 0
    cudaEventRecord(evFork, 0);
    cudaStreamWaitEvent(s1, evFork, 0);

    prep_split<<<2688, 256, 0, s1>>>(x, (const float*)d_in[3], (const float*)d_in[4],
                                     (const float*)d_in[5], (const float*)d_in[10],
                                     (const float*)d_in[12]);
    tcmma<<<dim3(32, 4, 3), 256, MM_SMEM, s1>>>(xhi, xlo, 0, qraw);

    detlut_kernel<<<264, 256>>>((const unsigned*)mask, pw1, pb1, pw2, pb2);
    maskfuse_kernel<<<4096, 256>>>(rel, mask);

    cudaEventRecord(evJoin, s1);
    cudaStreamWaitEvent(0, evJoin, 0);

    attn_mma_kernel<<<dim3(8, 32), 256, AT_SMEM>>>();

    // fused tail: GEMM + residual LN in one kernel each
    tcmma_ln<<<128, 256, FL_SMEM>>>(athi, atlo, 3, bo, x, g1, be1, zz, zhi, zlo, 0);
    tcmma_ln<<<128, 256, FL_SMEM>>>(zhi, zlo, 4, bfv, zz, g2, be2, (float*)d_out,
                                    nullptr, nullptr, 1);
}